// round 3
// baseline (speedup 1.0000x reference)
#include <cuda_runtime.h>
#include <cuda_bf16.h>

#define SRC_H 512
#define SRC_W 512
#define NCH   3
#define OUT_N 224
#define TOX   32   // output tile width
#define TOY   8    // output tile height
#define NTAP  6
#define NIX   79   // warped tile width
#define NIY   24   // warped tile height
#define NTHREADS 256

// staged source region capacity (per CTA, in SMEM)
#define SH_T  48
#define SW_T  100
#define SRC_FLOATS (SH_T * SW_T * NCH)          // 14400 floats = 57.6 KB
#define SW_FLOATS  (NCH * NIY * NIX)            // 5688  floats = 22.75 KB
#define ST_FLOATS  (NCH * NIY * TOX)            // 2304  floats = 9.2 KB
#define DYN_BYTES  ((SRC_FLOATS + SW_FLOATS + ST_FLOATS) * 4)

__global__ __launch_bounds__(NTHREADS) void warp_resize_kernel(
    const float* __restrict__ images,   // (32, 512, 512, 3)
    const float* __restrict__ mats,     // (32, 2, 3)
    float* __restrict__ out)            // (32, 224, 224, 3)
{
    extern __shared__ float dyn[];
    float* s_src = dyn;                       // [hgt][wid*3] (tight pitch)
    float* s_w   = dyn + SRC_FLOATS;          // [NCH][NIY][NIX]
    float* s_t   = s_w + SW_FLOATS;           // [NCH][NIY][TOX]

    __shared__ float s_wx[TOX][NTAP];
    __shared__ float s_wy[TOY][NTAP];
    __shared__ int   s_bx[TOX];
    __shared__ int   s_by[TOY];

    const int b   = blockIdx.z;
    const int ox0 = blockIdx.x * TOX;
    const int oy0 = blockIdx.y * TOY;
    const int tid = threadIdx.x;

    const float INV = 512.0f / 224.0f;
    const float SC  = 224.0f / 512.0f;

    const int IX0 = (int)floorf((ox0 + 0.5f) * INV - 0.5f) - 2;
    const int IY0 = (int)floorf((oy0 + 0.5f) * INV - 0.5f) - 2;

    // ---- Resize weights (normalized triangle kernel, jax semantics) ----
    if (tid < TOX) {
        int j = ox0 + tid;
        float sf = (j + 0.5f) * INV - 0.5f;
        int i0 = (int)floorf(sf) - 2;
        float wv[NTAP];
        float sum = 0.0f;
        #pragma unroll
        for (int k = 0; k < NTAP; k++) {
            int i = i0 + k;
            float w = fmaxf(1.0f - fabsf(sf - (float)i) * SC, 0.0f);
            if (i < 0 || i >= SRC_W) w = 0.0f;
            wv[k] = w; sum += w;
        }
        float inv = 1.0f / sum;
        #pragma unroll
        for (int k = 0; k < NTAP; k++) s_wx[tid][k] = wv[k] * inv;
        s_bx[tid] = i0 - IX0;
    } else if (tid < TOX + TOY) {
        int t = tid - TOX;
        int j = oy0 + t;
        float sf = (j + 0.5f) * INV - 0.5f;
        int i0 = (int)floorf(sf) - 2;
        float wv[NTAP];
        float sum = 0.0f;
        #pragma unroll
        for (int k = 0; k < NTAP; k++) {
            int i = i0 + k;
            float w = fmaxf(1.0f - fabsf(sf - (float)i) * SC, 0.0f);
            if (i < 0 || i >= SRC_H) w = 0.0f;
            wv[k] = w; sum += w;
        }
        float inv = 1.0f / sum;
        #pragma unroll
        for (int k = 0; k < NTAP; k++) s_wy[t][k] = wv[k] * inv;
        s_by[t] = i0 - IY0;
    }

    // ---- Affine matrix ----
    const float* Mp = mats + b * 6;
    const float M00 = __ldg(Mp + 0), M01 = __ldg(Mp + 1), M02 = __ldg(Mp + 2);
    const float M10 = __ldg(Mp + 3), M11 = __ldg(Mp + 4), M12 = __ldg(Mp + 5);

    const float* img = images + (size_t)b * SRC_H * SRC_W * NCH;

    // ---- Exact affine bounding box of the warped tile's source footprint ----
    // (affine over a rectangle attains extrema at the 4 corners)
    const float gy0 = (float)IY0, gy1 = (float)(IY0 + NIY - 1);
    const float gx0 = (float)IX0, gx1 = (float)(IX0 + NIX - 1);

    float sy00 = fmaf(M00, gy0, fmaf(M01, gx0, M02));
    float sy01 = fmaf(M00, gy0, fmaf(M01, gx1, M02));
    float sy10 = fmaf(M00, gy1, fmaf(M01, gx0, M02));
    float sy11 = fmaf(M00, gy1, fmaf(M01, gx1, M02));
    float sx00 = fmaf(M10, gy0, fmaf(M11, gx0, M12));
    float sx01 = fmaf(M10, gy0, fmaf(M11, gx1, M12));
    float sx10 = fmaf(M10, gy1, fmaf(M11, gx0, M12));
    float sx11 = fmaf(M10, gy1, fmaf(M11, gx1, M12));

    float symin = fminf(fminf(sy00, sy01), fminf(sy10, sy11));
    float symax = fmaxf(fmaxf(sy00, sy01), fmaxf(sy10, sy11));
    float sxmin = fminf(fminf(sx00, sx01), fminf(sx10, sx11));
    float sxmax = fmaxf(fmaxf(sx00, sx01), fmaxf(sx10, sx11));

    int by0 = max(0, (int)floorf(symin) - 1);
    int by1 = min(SRC_H - 1, (int)floorf(symax) + 2);
    int bx0 = max(0, (int)floorf(sxmin) - 1);
    int bx1 = min(SRC_W - 1, (int)floorf(sxmax) + 2);

    int hgt = by1 - by0 + 1;
    int wid = bx1 - bx0 + 1;
    bool staged = (hgt > 0) && (wid > 0) && (hgt <= SH_T) && (wid <= SW_T);

    if (staged) {
        // ---- Stage source region into SMEM (coalesced) ----
        const int w3 = wid * NCH;
        const float* grow = img + ((size_t)by0 * SRC_W + bx0) * NCH;
        for (int r = 0; r < hgt; r++) {
            const float* gr = grow + (size_t)r * SRC_W * NCH;
            float* sr = s_src + r * w3;
            for (int ci = tid; ci < w3; ci += NTHREADS) sr[ci] = gr[ci];
        }
        __syncthreads();

        // ---- Stage 1: warped tile via SMEM bilerp ----
        for (int idx = tid; idx < NIY * NIX; idx += NTHREADS) {
            int ty = idx / NIX;
            int tx = idx - ty * NIX;
            float gy = (float)(IY0 + ty);
            float gx = (float)(IX0 + tx);
            float sy = fmaf(M00, gy, fmaf(M01, gx, M02));
            float sx = fmaf(M10, gy, fmaf(M11, gx, M12));
            float fy = floorf(sy), fx = floorf(sx);
            float ay = sy - fy,   ax = sx - fx;
            int y0 = (int)fy, x0 = (int)fx;

            float r = 0.0f, g = 0.0f, bl = 0.0f;
            #pragma unroll
            for (int dy = 0; dy < 2; dy++) {
                int yi = y0 + dy;
                float wy = dy ? ay : (1.0f - ay);
                bool vy = (yi >= 0) & (yi < SRC_H);
                #pragma unroll
                for (int dx = 0; dx < 2; dx++) {
                    int xi = x0 + dx;
                    float w = wy * (dx ? ax : (1.0f - ax));
                    if (vy & (xi >= 0) & (xi < SRC_W)) {
                        // valid corners are guaranteed inside the staged bbox
                        const float* p = s_src + ((yi - by0) * wid + (xi - bx0)) * NCH;
                        r  = fmaf(w, p[0], r);
                        g  = fmaf(w, p[1], g);
                        bl = fmaf(w, p[2], bl);
                    }
                }
            }
            s_w[(0 * NIY + ty) * NIX + tx] = r;
            s_w[(1 * NIY + ty) * NIX + tx] = g;
            s_w[(2 * NIY + ty) * NIX + tx] = bl;
        }
    } else {
        // ---- Fallback: global gathers (correctness safety net) ----
        __syncthreads();  // keep barrier count uniform with staged path
        for (int idx = tid; idx < NIY * NIX; idx += NTHREADS) {
            int ty = idx / NIX;
            int tx = idx - ty * NIX;
            float gy = (float)(IY0 + ty);
            float gx = (float)(IX0 + tx);
            float sy = fmaf(M00, gy, fmaf(M01, gx, M02));
            float sx = fmaf(M10, gy, fmaf(M11, gx, M12));
            float fy = floorf(sy), fx = floorf(sx);
            float ay = sy - fy,   ax = sx - fx;
            int y0 = (int)fy, x0 = (int)fx;

            float r = 0.0f, g = 0.0f, bl = 0.0f;
            #pragma unroll
            for (int dy = 0; dy < 2; dy++) {
                int yi = y0 + dy;
                float wy = dy ? ay : (1.0f - ay);
                bool vy = (yi >= 0) & (yi < SRC_H);
                #pragma unroll
                for (int dx = 0; dx < 2; dx++) {
                    int xi = x0 + dx;
                    float w = wy * (dx ? ax : (1.0f - ax));
                    if (vy & (xi >= 0) & (xi < SRC_W)) {
                        const float* p = img + ((size_t)yi * SRC_W + xi) * NCH;
                        r  = fmaf(w, p[0], r);
                        g  = fmaf(w, p[1], g);
                        bl = fmaf(w, p[2], bl);
                    }
                }
            }
            s_w[(0 * NIY + ty) * NIX + tx] = r;
            s_w[(1 * NIY + ty) * NIX + tx] = g;
            s_w[(2 * NIY + ty) * NIX + tx] = bl;
        }
    }
    __syncthreads();

    // ---- Stage 2: x-convolution (6 taps) ----
    for (int idx = tid; idx < NIY * TOX; idx += NTHREADS) {
        int ty = idx / TOX;
        int ox = idx - ty * TOX;
        int base = s_bx[ox];
        float a0 = 0.0f, a1 = 0.0f, a2 = 0.0f;
        #pragma unroll
        for (int k = 0; k < NTAP; k++) {
            float w = s_wx[ox][k];
            a0 = fmaf(w, s_w[(0 * NIY + ty) * NIX + base + k], a0);
            a1 = fmaf(w, s_w[(1 * NIY + ty) * NIX + base + k], a1);
            a2 = fmaf(w, s_w[(2 * NIY + ty) * NIX + base + k], a2);
        }
        s_t[(0 * NIY + ty) * TOX + ox] = a0;
        s_t[(1 * NIY + ty) * TOX + ox] = a1;
        s_t[(2 * NIY + ty) * TOX + ox] = a2;
    }
    __syncthreads();

    // ---- Stage 3: y-convolution (6 taps) + coalesced store ----
    {
        int oy = tid / TOX;
        int ox = tid - oy * TOX;
        int base = s_by[oy];
        float a0 = 0.0f, a1 = 0.0f, a2 = 0.0f;
        #pragma unroll
        for (int k = 0; k < NTAP; k++) {
            float w = s_wy[oy][k];
            a0 = fmaf(w, s_t[(0 * NIY + base + k) * TOX + ox], a0);
            a1 = fmaf(w, s_t[(1 * NIY + base + k) * TOX + ox], a1);
            a2 = fmaf(w, s_t[(2 * NIY + base + k) * TOX + ox], a2);
        }
        float* op = out + (((size_t)b * OUT_N + (oy0 + oy)) * OUT_N + (ox0 + ox)) * NCH;
        op[0] = a0;
        op[1] = a1;
        op[2] = a2;
    }
}

extern "C" void kernel_launch(void* const* d_in, const int* in_sizes, int n_in,
                              void* d_out, int out_size)
{
    const float* images = (const float*)d_in[0];
    const float* mats   = (const float*)d_in[1];
    float* out = (float*)d_out;

    cudaFuncSetAttribute(warp_resize_kernel,
                         cudaFuncAttributeMaxDynamicSharedMemorySize, DYN_BYTES);

    dim3 grid(OUT_N / TOX, OUT_N / TOY, 32);   // 7 x 28 x 32
    warp_resize_kernel<<<grid, NTHREADS, DYN_BYTES>>>(images, mats, out);
}

// round 4
// speedup vs baseline: 2.5715x; 2.5715x over previous
#include <cuda_runtime.h>
#include <cuda_bf16.h>

#define SRC_H 512
#define SRC_W 512
#define NCH   3
#define OUT_N 224
#define TOX   32   // output tile width
#define TOY   8    // output tile height
#define NTAP  6
#define NIX   79   // warped tile width
#define NIY   24   // warped tile height
#define NTHREADS 256

__global__ __launch_bounds__(NTHREADS) void warp_resize_kernel(
    const float* __restrict__ images,   // (32, 512, 512, 3)
    const float* __restrict__ mats,     // (32, 2, 3)
    float* __restrict__ out)            // (32, 224, 224, 3)
{
    __shared__ float s_w[NCH][NIY][NIX];     // warped tile
    __shared__ float s_t[NCH][NIY][TOX];     // after x-convolution
    __shared__ float s_wx[TOX][NTAP];
    __shared__ float s_wy[TOY][NTAP];
    __shared__ int   s_bx[TOX];
    __shared__ int   s_by[TOY];

    const int b   = blockIdx.z;
    const int ox0 = blockIdx.x * TOX;
    const int oy0 = blockIdx.y * TOY;
    const int tid = threadIdx.x;

    const float INV = 512.0f / 224.0f;   // inv_scale = kernel_scale (antialias downscale)
    const float SC  = 224.0f / 512.0f;

    const int IX0 = (int)floorf((ox0 + 0.5f) * INV - 0.5f) - 2;
    const int IY0 = (int)floorf((oy0 + 0.5f) * INV - 0.5f) - 2;

    // ---- Resize weights (normalized triangle kernel, jax semantics) ----
    if (tid < TOX) {
        int j = ox0 + tid;
        float sf = (j + 0.5f) * INV - 0.5f;
        int i0 = (int)floorf(sf) - 2;
        float wv[NTAP];
        float sum = 0.0f;
        #pragma unroll
        for (int k = 0; k < NTAP; k++) {
            int i = i0 + k;
            float w = fmaxf(1.0f - fabsf(sf - (float)i) * SC, 0.0f);
            if (i < 0 || i >= SRC_W) w = 0.0f;
            wv[k] = w; sum += w;
        }
        float inv = 1.0f / sum;
        #pragma unroll
        for (int k = 0; k < NTAP; k++) s_wx[tid][k] = wv[k] * inv;
        s_bx[tid] = i0 - IX0;
    } else if (tid < TOX + TOY) {
        int t = tid - TOX;
        int j = oy0 + t;
        float sf = (j + 0.5f) * INV - 0.5f;
        int i0 = (int)floorf(sf) - 2;
        float wv[NTAP];
        float sum = 0.0f;
        #pragma unroll
        for (int k = 0; k < NTAP; k++) {
            int i = i0 + k;
            float w = fmaxf(1.0f - fabsf(sf - (float)i) * SC, 0.0f);
            if (i < 0 || i >= SRC_H) w = 0.0f;
            wv[k] = w; sum += w;
        }
        float inv = 1.0f / sum;
        #pragma unroll
        for (int k = 0; k < NTAP; k++) s_wy[t][k] = wv[k] * inv;
        s_by[t] = i0 - IY0;
    }

    // ---- Affine matrix for this batch ----
    const float* Mp = mats + b * 6;
    const float M00 = __ldg(Mp + 0), M01 = __ldg(Mp + 1), M02 = __ldg(Mp + 2);
    const float M10 = __ldg(Mp + 3), M11 = __ldg(Mp + 4), M12 = __ldg(Mp + 5);

    const float* img = images + (size_t)b * SRC_H * SRC_W * NCH;

    // ---- Stage 1: warped tile at FLOAT granularity ----
    // idx -> (pixel, channel) with channel fastest: consecutive lanes touch
    // nearly-consecutive source floats -> ~1 L1 wavefront per warp-LDG.
    #pragma unroll 2
    for (int idx = tid; idx < NIY * NIX * NCH; idx += NTHREADS) {
        int c   = idx % NCH;
        int pix = idx / NCH;
        int ty  = pix / NIX;
        int tx  = pix - ty * NIX;

        float gy = (float)(IY0 + ty);
        float gx = (float)(IX0 + tx);
        float sy = fmaf(M00, gy, fmaf(M01, gx, M02));
        float sx = fmaf(M10, gy, fmaf(M11, gx, M12));
        float fy = floorf(sy), fx = floorf(sx);
        float ay = sy - fy,   ax = sx - fx;
        int y0 = (int)fy, x0 = (int)fx;

        float acc = 0.0f;
        #pragma unroll
        for (int dy = 0; dy < 2; dy++) {
            int yi = y0 + dy;
            float wy = dy ? ay : (1.0f - ay);
            bool vy = (yi >= 0) & (yi < SRC_H);
            #pragma unroll
            for (int dx = 0; dx < 2; dx++) {
                int xi = x0 + dx;
                float w = wy * (dx ? ax : (1.0f - ax));
                if (vy & (xi >= 0) & (xi < SRC_W)) {
                    acc = fmaf(w, __ldg(img + ((size_t)yi * SRC_W + xi) * NCH + c), acc);
                }
            }
        }
        s_w[c][ty][tx] = acc;
    }
    __syncthreads();

    // ---- Stage 2: x-convolution (6 taps) ----
    for (int idx = tid; idx < NIY * TOX; idx += NTHREADS) {
        int ty = idx / TOX;
        int ox = idx - ty * TOX;
        int base = s_bx[ox];
        float a0 = 0.0f, a1 = 0.0f, a2 = 0.0f;
        #pragma unroll
        for (int k = 0; k < NTAP; k++) {
            float w = s_wx[ox][k];
            a0 = fmaf(w, s_w[0][ty][base + k], a0);
            a1 = fmaf(w, s_w[1][ty][base + k], a1);
            a2 = fmaf(w, s_w[2][ty][base + k], a2);
        }
        s_t[0][ty][ox] = a0;
        s_t[1][ty][ox] = a1;
        s_t[2][ty][ox] = a2;
    }
    __syncthreads();

    // ---- Stage 3: y-convolution (6 taps) + coalesced store ----
    {
        int oy = tid / TOX;      // 0..7  (256 = 8*32 exactly)
        int ox = tid - oy * TOX; // 0..31
        int base = s_by[oy];
        float a0 = 0.0f, a1 = 0.0f, a2 = 0.0f;
        #pragma unroll
        for (int k = 0; k < NTAP; k++) {
            float w = s_wy[oy][k];
            a0 = fmaf(w, s_t[0][base + k][ox], a0);
            a1 = fmaf(w, s_t[1][base + k][ox], a1);
            a2 = fmaf(w, s_t[2][base + k][ox], a2);
        }
        float* op = out + (((size_t)b * OUT_N + (oy0 + oy)) * OUT_N + (ox0 + ox)) * NCH;
        op[0] = a0;
        op[1] = a1;
        op[2] = a2;
    }
}

extern "C" void kernel_launch(void* const* d_in, const int* in_sizes, int n_in,
                              void* d_out, int out_size)
{
    const float* images = (const float*)d_in[0];   // 32*512*512*3 floats
    const float* mats   = (const float*)d_in[1];   // 32*2*3 floats
    float* out = (float*)d_out;                    // 32*224*224*3 floats

    dim3 grid(OUT_N / TOX, OUT_N / TOY, 32);       // 7 x 28 x 32
    warp_resize_kernel<<<grid, NTHREADS>>>(images, mats, out);
}

// round 5
// speedup vs baseline: 2.7939x; 1.0865x over previous
#include <cuda_runtime.h>
#include <cuda_fp16.h>
#include <cuda_bf16.h>

#define SRC_H 512
#define SRC_W 512
#define NCH   3
#define OUT_N 224
#define TOX   32
#define TOY   8
#define NTAP  6
#define NIX   79
#define NIY   24
#define NTHREADS 256

#define PLANE  (SRC_H * SRC_W)           // 262144
#define IMG3   (NCH * PLANE)             // 786432

// 50.3 MB planar fp16 scratch: layout (b, c, y, x)
__device__ __half g_plan[32 * IMG3];

// ---------------- Pre-pass: (b,y,x,c) fp32 -> (b,c,y,x) fp16 ----------------
__global__ __launch_bounds__(NTHREADS) void planarize_kernel(const float* __restrict__ in)
{
    __shared__ float s[NTHREADS * 3];
    const unsigned tid = threadIdx.x;
    const size_t base = (size_t)blockIdx.x * NTHREADS;      // pixel base
    const size_t fb = base * 3;
    s[tid]       = in[fb + tid];
    s[tid + 256] = in[fb + tid + 256];
    s[tid + 512] = in[fb + tid + 512];
    __syncthreads();
    const unsigned P = (unsigned)base + tid;
    const unsigned b = P >> 18;             // / PLANE
    const unsigned local = P & (PLANE - 1);
    __half* dst = g_plan + (size_t)b * IMG3 + local;
    dst[0]         = __float2half_rn(s[tid * 3 + 0]);
    dst[PLANE]     = __float2half_rn(s[tid * 3 + 1]);
    dst[2 * PLANE] = __float2half_rn(s[tid * 3 + 2]);
}

// ---------------- Main: fused warp + separable antialiased resize ----------------
__global__ __launch_bounds__(NTHREADS) void warp_resize_kernel(
    const float* __restrict__ mats,     // (32, 2, 3)
    float* __restrict__ out)            // (32, 224, 224, 3)
{
    __shared__ float s_w[NCH][NIY][NIX];
    __shared__ float s_t[NCH][NIY][TOX];
    __shared__ float s_wx[TOX][NTAP];
    __shared__ float s_wy[TOY][NTAP];
    __shared__ int   s_bx[TOX];
    __shared__ int   s_by[TOY];

    const int b   = blockIdx.z;
    const int ox0 = blockIdx.x * TOX;
    const int oy0 = blockIdx.y * TOY;
    const int tid = threadIdx.x;
    const int wid = tid >> 5;
    const int lane = tid & 31;

    const float INV = 512.0f / 224.0f;
    const float SC  = 224.0f / 512.0f;

    const int IX0 = (int)floorf((ox0 + 0.5f) * INV - 0.5f) - 2;
    const int IY0 = (int)floorf((oy0 + 0.5f) * INV - 0.5f) - 2;

    // ---- Resize weights (normalized triangle kernel, jax semantics) ----
    if (tid < TOX) {
        int j = ox0 + tid;
        float sf = (j + 0.5f) * INV - 0.5f;
        int i0 = (int)floorf(sf) - 2;
        float wv[NTAP];
        float sum = 0.0f;
        #pragma unroll
        for (int k = 0; k < NTAP; k++) {
            int i = i0 + k;
            float w = fmaxf(1.0f - fabsf(sf - (float)i) * SC, 0.0f);
            if (i < 0 || i >= SRC_W) w = 0.0f;
            wv[k] = w; sum += w;
        }
        float inv = 1.0f / sum;
        #pragma unroll
        for (int k = 0; k < NTAP; k++) s_wx[tid][k] = wv[k] * inv;
        s_bx[tid] = i0 - IX0;
    } else if (tid < TOX + TOY) {
        int t = tid - TOX;
        int j = oy0 + t;
        float sf = (j + 0.5f) * INV - 0.5f;
        int i0 = (int)floorf(sf) - 2;
        float wv[NTAP];
        float sum = 0.0f;
        #pragma unroll
        for (int k = 0; k < NTAP; k++) {
            int i = i0 + k;
            float w = fmaxf(1.0f - fabsf(sf - (float)i) * SC, 0.0f);
            if (i < 0 || i >= SRC_H) w = 0.0f;
            wv[k] = w; sum += w;
        }
        float inv = 1.0f / sum;
        #pragma unroll
        for (int k = 0; k < NTAP; k++) s_wy[t][k] = wv[k] * inv;
        s_by[t] = i0 - IY0;
    }

    const float* Mp = mats + b * 6;
    const float M00 = __ldg(Mp + 0), M01 = __ldg(Mp + 1), M02 = __ldg(Mp + 2);
    const float M10 = __ldg(Mp + 3), M11 = __ldg(Mp + 4), M12 = __ldg(Mp + 5);

    const __half* pb = g_plan + (size_t)b * IMG3;

    // ---- Stage 1: warped tile; warp-uniform rows, lanes along x (coalesced fp16 gathers) ----
    // 72 warp-tasks: (row ty, 32-wide chunk); 8 warps -> 9 iterations each.
    for (int it = wid; it < NIY * 3; it += 8) {
        int ty    = it / 3;
        int chunk = it - ty * 3;
        int tx    = chunk * 32 + lane;
        if (tx < NIX) {
            float gy = (float)(IY0 + ty);
            float gx = (float)(IX0 + tx);
            float sy = fmaf(M00, gy, fmaf(M01, gx, M02));
            float sx = fmaf(M10, gy, fmaf(M11, gx, M12));
            float fy = floorf(sy), fx = floorf(sx);
            float ay = sy - fy,   ax = sx - fx;
            int y0 = (int)fy, x0 = (int)fx;
            int y1 = y0 + 1,  x1 = x0 + 1;
            bool vy0 = (unsigned)y0 < (unsigned)SRC_H;
            bool vy1 = (unsigned)y1 < (unsigned)SRC_H;
            bool vx0 = (unsigned)x0 < (unsigned)SRC_W;
            bool vx1 = (unsigned)x1 < (unsigned)SRC_W;
            int r0 = y0 * SRC_W;
            int r1 = r0 + SRC_W;
            float w00 = (1.0f - ay) * (1.0f - ax);
            float w01 = (1.0f - ay) * ax;
            float w10 = ay * (1.0f - ax);
            float w11 = ay * ax;

            float r = 0.0f, g = 0.0f, bl = 0.0f;
            if (vy0 & vx0) {
                const __half* p = pb + r0 + x0;
                r  = fmaf(w00, __half2float(__ldg(p)),             r);
                g  = fmaf(w00, __half2float(__ldg(p + PLANE)),     g);
                bl = fmaf(w00, __half2float(__ldg(p + 2 * PLANE)), bl);
            }
            if (vy0 & vx1) {
                const __half* p = pb + r0 + x1;
                r  = fmaf(w01, __half2float(__ldg(p)),             r);
                g  = fmaf(w01, __half2float(__ldg(p + PLANE)),     g);
                bl = fmaf(w01, __half2float(__ldg(p + 2 * PLANE)), bl);
            }
            if (vy1 & vx0) {
                const __half* p = pb + r1 + x0;
                r  = fmaf(w10, __half2float(__ldg(p)),             r);
                g  = fmaf(w10, __half2float(__ldg(p + PLANE)),     g);
                bl = fmaf(w10, __half2float(__ldg(p + 2 * PLANE)), bl);
            }
            if (vy1 & vx1) {
                const __half* p = pb + r1 + x1;
                r  = fmaf(w11, __half2float(__ldg(p)),             r);
                g  = fmaf(w11, __half2float(__ldg(p + PLANE)),     g);
                bl = fmaf(w11, __half2float(__ldg(p + 2 * PLANE)), bl);
            }
            s_w[0][ty][tx] = r;
            s_w[1][ty][tx] = g;
            s_w[2][ty][tx] = bl;
        }
    }
    __syncthreads();

    // ---- Stage 2: x-convolution (6 taps) ----
    for (int idx = tid; idx < NIY * TOX; idx += NTHREADS) {
        int ty = idx / TOX;
        int ox = idx - ty * TOX;
        int base = s_bx[ox];
        float a0 = 0.0f, a1 = 0.0f, a2 = 0.0f;
        #pragma unroll
        for (int k = 0; k < NTAP; k++) {
            float w = s_wx[ox][k];
            a0 = fmaf(w, s_w[0][ty][base + k], a0);
            a1 = fmaf(w, s_w[1][ty][base + k], a1);
            a2 = fmaf(w, s_w[2][ty][base + k], a2);
        }
        s_t[0][ty][ox] = a0;
        s_t[1][ty][ox] = a1;
        s_t[2][ty][ox] = a2;
    }
    __syncthreads();

    // ---- Stage 3: y-convolution (6 taps) + coalesced store ----
    {
        int oy = tid / TOX;
        int ox = tid - oy * TOX;
        int base = s_by[oy];
        float a0 = 0.0f, a1 = 0.0f, a2 = 0.0f;
        #pragma unroll
        for (int k = 0; k < NTAP; k++) {
            float w = s_wy[oy][k];
            a0 = fmaf(w, s_t[0][base + k][ox], a0);
            a1 = fmaf(w, s_t[1][base + k][ox], a1);
            a2 = fmaf(w, s_t[2][base + k][ox], a2);
        }
        float* op = out + (((size_t)b * OUT_N + (oy0 + oy)) * OUT_N + (ox0 + ox)) * NCH;
        op[0] = a0;
        op[1] = a1;
        op[2] = a2;
    }
}

extern "C" void kernel_launch(void* const* d_in, const int* in_sizes, int n_in,
                              void* d_out, int out_size)
{
    const float* images = (const float*)d_in[0];
    const float* mats   = (const float*)d_in[1];
    float* out = (float*)d_out;

    // Pre-pass: 32*512*512 pixels / 256 per CTA = 32768 CTAs
    planarize_kernel<<<32 * PLANE / NTHREADS, NTHREADS>>>(images);

    dim3 grid(OUT_N / TOX, OUT_N / TOY, 32);   // 7 x 28 x 32
    warp_resize_kernel<<<grid, NTHREADS>>>(mats, out);
}

// round 6
// speedup vs baseline: 3.0000x; 1.0738x over previous
#include <cuda_runtime.h>
#include <cuda_fp16.h>
#include <cuda_bf16.h>

#define SRC_H 512
#define SRC_W 512
#define NCH   3
#define OUT_N 224
#define TOX   32
#define TOY   8
#define NTAP  6
#define NIX   79
#define NIXP  80
#define NIY   24
#define NTHREADS 256

#define SH_T  48            // staged box max height
#define SW_T  106           // staged box max width (pixels)
#define PITCH_H 320         // halfs per staged row  (>= SW_T*3, multiple of 4)
#define ROWF  (SRC_W * NCH) // 1536 floats per image row
#define TOTF  ((size_t)32 * SRC_H * SRC_W * NCH)

// dynamic SMEM layout (bytes)
#define OFF_SRC  0
#define SZ_SRC   (SH_T * PITCH_H * 2)                 // 30720
#define OFF_WRG  (OFF_SRC + SZ_SRC)
#define SZ_WRG   (NIY * NIXP * 4)                     // 7680 (half2)
#define OFF_WB   (OFF_WRG + SZ_WRG)
#define SZ_WB    (NIY * NIXP * 2)                     // 3840 (half)
#define OFF_TRG  (OFF_WB + SZ_WB)
#define SZ_TRG   (NIY * TOX * 8)                      // 6144 (float2)
#define OFF_TB   (OFF_TRG + SZ_TRG)
#define SZ_TB    (NIY * TOX * 4)                      // 3072 (float)
#define DYN_BYTES (OFF_TB + SZ_TB)                    // 51456

__global__ __launch_bounds__(NTHREADS) void warp_resize_kernel(
    const float* __restrict__ images,   // (32, 512, 512, 3)
    const float* __restrict__ mats,     // (32, 2, 3)
    float* __restrict__ out)            // (32, 224, 224, 3)
{
    extern __shared__ __align__(16) unsigned char dynraw[];
    __half*  s_src = (__half*) (dynraw + OFF_SRC);
    __half2* s_wRG = (__half2*)(dynraw + OFF_WRG);
    __half*  s_wB  = (__half*) (dynraw + OFF_WB);
    float2*  s_tRG = (float2*) (dynraw + OFF_TRG);
    float*   s_tB  = (float*)  (dynraw + OFF_TB);

    __shared__ float s_wx[TOX][NTAP];
    __shared__ float s_wy[TOY][NTAP];
    __shared__ int   s_bx[TOX];
    __shared__ int   s_by[TOY];

    const int b   = blockIdx.z;
    const int ox0 = blockIdx.x * TOX;
    const int oy0 = blockIdx.y * TOY;
    const int tid = threadIdx.x;
    const int wrp = tid >> 5;
    const int lane = tid & 31;

    const float INV = 512.0f / 224.0f;
    const float SC  = 224.0f / 512.0f;

    const int IX0 = (int)floorf((ox0 + 0.5f) * INV - 0.5f) - 2;
    const int IY0 = (int)floorf((oy0 + 0.5f) * INV - 0.5f) - 2;

    // ---- Resize weights (normalized triangle kernel, jax semantics) ----
    if (tid < TOX) {
        int j = ox0 + tid;
        float sf = (j + 0.5f) * INV - 0.5f;
        int i0 = (int)floorf(sf) - 2;
        float wv[NTAP];
        float sum = 0.0f;
        #pragma unroll
        for (int k = 0; k < NTAP; k++) {
            int i = i0 + k;
            float w = fmaxf(1.0f - fabsf(sf - (float)i) * SC, 0.0f);
            if (i < 0 || i >= SRC_W) w = 0.0f;
            wv[k] = w; sum += w;
        }
        float inv = 1.0f / sum;
        #pragma unroll
        for (int k = 0; k < NTAP; k++) s_wx[tid][k] = wv[k] * inv;
        s_bx[tid] = i0 - IX0;
    } else if (tid < TOX + TOY) {
        int t = tid - TOX;
        int j = oy0 + t;
        float sf = (j + 0.5f) * INV - 0.5f;
        int i0 = (int)floorf(sf) - 2;
        float wv[NTAP];
        float sum = 0.0f;
        #pragma unroll
        for (int k = 0; k < NTAP; k++) {
            int i = i0 + k;
            float w = fmaxf(1.0f - fabsf(sf - (float)i) * SC, 0.0f);
            if (i < 0 || i >= SRC_H) w = 0.0f;
            wv[k] = w; sum += w;
        }
        float inv = 1.0f / sum;
        #pragma unroll
        for (int k = 0; k < NTAP; k++) s_wy[t][k] = wv[k] * inv;
        s_by[t] = i0 - IY0;
    }

    const float* Mp = mats + b * 6;
    const float M00 = __ldg(Mp + 0), M01 = __ldg(Mp + 1), M02 = __ldg(Mp + 2);
    const float M10 = __ldg(Mp + 3), M11 = __ldg(Mp + 4), M12 = __ldg(Mp + 5);

    const float* img = images + (size_t)b * SRC_H * SRC_W * NCH;

    // ---- Exact affine bbox of the warped tile's source footprint ----
    const float gy0 = (float)IY0, gy1 = (float)(IY0 + NIY - 1);
    const float gx0 = (float)IX0, gx1 = (float)(IX0 + NIX - 1);

    float sy00 = fmaf(M00, gy0, fmaf(M01, gx0, M02));
    float sy01 = fmaf(M00, gy0, fmaf(M01, gx1, M02));
    float sy10 = fmaf(M00, gy1, fmaf(M01, gx0, M02));
    float sy11 = fmaf(M00, gy1, fmaf(M01, gx1, M02));
    float sx00 = fmaf(M10, gy0, fmaf(M11, gx0, M12));
    float sx01 = fmaf(M10, gy0, fmaf(M11, gx1, M12));
    float sx10 = fmaf(M10, gy1, fmaf(M11, gx0, M12));
    float sx11 = fmaf(M10, gy1, fmaf(M11, gx1, M12));

    float symin = fminf(fminf(sy00, sy01), fminf(sy10, sy11));
    float symax = fmaxf(fmaxf(sy00, sy01), fmaxf(sy10, sy11));
    float sxmin = fminf(fminf(sx00, sx01), fminf(sx10, sx11));
    float sxmax = fmaxf(fmaxf(sx00, sx01), fmaxf(sx10, sx11));

    int by0 = max(0, (int)floorf(symin) - 1);
    int by1 = min(SRC_H - 1, (int)floorf(symax) + 2);
    int bx0 = max(0, ((int)floorf(sxmin) - 1)) & ~3;   // align to 4 px for float4 staging
    int bx1 = min(SRC_W - 1, (int)floorf(sxmax) + 2);

    int hgt = by1 - by0 + 1;
    int wid = bx1 - bx0 + 1;
    bool staged = (hgt > 0) && (wid > 0) && (hgt <= SH_T) && (wid <= SW_T);

    // ---- Stage source box into SMEM as fp16 interleaved (coalesced float4) ----
    if (staged) {
        int wid3   = wid * NCH;
        int n4     = (wid3 + 3) >> 2;       // float4s per row
        int total4 = hgt * n4;
        size_t base_f = (size_t)b * SRC_H * SRC_W * NCH + ((size_t)by0 * SRC_W + bx0) * NCH;
        for (int i = tid; i < total4; i += NTHREADS) {
            int r = i / n4;
            int j = i - r * n4;
            size_t fidx = base_f + (size_t)r * ROWF + (size_t)j * 4;
            const float* gp = images + fidx;
            float4 v;
            if (fidx + 4 <= TOTF) {
                v = *reinterpret_cast<const float4*>(gp);
            } else {
                v.x = (fidx + 0 < TOTF) ? gp[0] : 0.0f;
                v.y = (fidx + 1 < TOTF) ? gp[1] : 0.0f;
                v.z = (fidx + 2 < TOTF) ? gp[2] : 0.0f;
                v.w = 0.0f;
            }
            __half2* dst = (__half2*)(s_src + r * PITCH_H + j * 4);
            dst[0] = __floats2half2_rn(v.x, v.y);
            dst[1] = __floats2half2_rn(v.z, v.w);
        }
    }
    __syncthreads();

    // ---- Stage 1: warped tile (branch-free clamped gathers) ----
    for (int t = wrp; t < NIY * 3; t += 8) {
        int ty    = t / 3;
        int chunk = t - ty * 3;
        int tx    = chunk * 32 + lane;
        if (tx < NIX) {
            float gy = (float)(IY0 + ty);
            float gx = (float)(IX0 + tx);
            float sy = fmaf(M00, gy, fmaf(M01, gx, M02));
            float sx = fmaf(M10, gy, fmaf(M11, gx, M12));
            float fy = floorf(sy), fx = floorf(sx);
            float ay = sy - fy,   ax = sx - fx;
            int y0 = (int)fy, x0 = (int)fx;
            int y1 = y0 + 1,  x1 = x0 + 1;
            bool vy0 = (unsigned)y0 < (unsigned)SRC_H;
            bool vy1 = (unsigned)y1 < (unsigned)SRC_H;
            bool vx0 = (unsigned)x0 < (unsigned)SRC_W;
            bool vx1 = (unsigned)x1 < (unsigned)SRC_W;
            float w00 = (vy0 & vx0) ? (1.0f - ay) * (1.0f - ax) : 0.0f;
            float w01 = (vy0 & vx1) ? (1.0f - ay) * ax : 0.0f;
            float w10 = (vy1 & vx0) ? ay * (1.0f - ax) : 0.0f;
            float w11 = (vy1 & vx1) ? ay * ax : 0.0f;

            float r, g, bl;
            if (staged) {
                int ry0 = min(max(y0 - by0, 0), hgt - 1);
                int ry1 = min(max(y1 - by0, 0), hgt - 1);
                int rx0 = min(max(x0 - bx0, 0), wid - 1);
                int rx1 = min(max(x1 - bx0, 0), wid - 1);
                const __half* p00 = s_src + ry0 * PITCH_H + rx0 * NCH;
                const __half* p01 = s_src + ry0 * PITCH_H + rx1 * NCH;
                const __half* p10 = s_src + ry1 * PITCH_H + rx0 * NCH;
                const __half* p11 = s_src + ry1 * PITCH_H + rx1 * NCH;
                r  = w00 * __half2float(p00[0]) + w01 * __half2float(p01[0])
                   + w10 * __half2float(p10[0]) + w11 * __half2float(p11[0]);
                g  = w00 * __half2float(p00[1]) + w01 * __half2float(p01[1])
                   + w10 * __half2float(p10[1]) + w11 * __half2float(p11[1]);
                bl = w00 * __half2float(p00[2]) + w01 * __half2float(p01[2])
                   + w10 * __half2float(p10[2]) + w11 * __half2float(p11[2]);
            } else {
                int cy0 = min(max(y0, 0), SRC_H - 1);
                int cy1 = min(max(y1, 0), SRC_H - 1);
                int cx0 = min(max(x0, 0), SRC_W - 1);
                int cx1 = min(max(x1, 0), SRC_W - 1);
                const float* p00 = img + ((size_t)cy0 * SRC_W + cx0) * NCH;
                const float* p01 = img + ((size_t)cy0 * SRC_W + cx1) * NCH;
                const float* p10 = img + ((size_t)cy1 * SRC_W + cx0) * NCH;
                const float* p11 = img + ((size_t)cy1 * SRC_W + cx1) * NCH;
                r  = w00 * p00[0] + w01 * p01[0] + w10 * p10[0] + w11 * p11[0];
                g  = w00 * p00[1] + w01 * p01[1] + w10 * p10[1] + w11 * p11[1];
                bl = w00 * p00[2] + w01 * p01[2] + w10 * p10[2] + w11 * p11[2];
            }
            s_wRG[ty * NIXP + tx] = __floats2half2_rn(r, g);
            s_wB [ty * NIXP + tx] = __float2half_rn(bl);
        }
    }
    __syncthreads();

    // ---- Stage 2: x-convolution (6 taps) ----
    for (int i = tid; i < NIY * TOX; i += NTHREADS) {
        int ty = i >> 5;          // TOX == 32
        int ox = i & 31;
        int base = s_bx[ox];
        const __half2* rowRG = s_wRG + ty * NIXP + base;
        const __half*  rowB  = s_wB  + ty * NIXP + base;
        float a0 = 0.0f, a1 = 0.0f, a2 = 0.0f;
        #pragma unroll
        for (int k = 0; k < NTAP; k++) {
            float w = s_wx[ox][k];
            float2 f = __half22float2(rowRG[k]);
            a0 = fmaf(w, f.x, a0);
            a1 = fmaf(w, f.y, a1);
            a2 = fmaf(w, __half2float(rowB[k]), a2);
        }
        s_tRG[ty * TOX + ox] = make_float2(a0, a1);
        s_tB [ty * TOX + ox] = a2;
    }
    __syncthreads();

    // ---- Stage 3: y-convolution (6 taps) + store ----
    {
        int oy = tid >> 5;        // 0..7
        int ox = tid & 31;        // 0..31
        int base = s_by[oy];
        float a0 = 0.0f, a1 = 0.0f, a2 = 0.0f;
        #pragma unroll
        for (int k = 0; k < NTAP; k++) {
            float w = s_wy[oy][k];
            float2 f = s_tRG[(base + k) * TOX + ox];
            a0 = fmaf(w, f.x, a0);
            a1 = fmaf(w, f.y, a1);
            a2 = fmaf(w, s_tB[(base + k) * TOX + ox], a2);
        }
        float* op = out + (((size_t)b * OUT_N + (oy0 + oy)) * OUT_N + (ox0 + ox)) * NCH;
        op[0] = a0;
        op[1] = a1;
        op[2] = a2;
    }
}

extern "C" void kernel_launch(void* const* d_in, const int* in_sizes, int n_in,
                              void* d_out, int out_size)
{
    const float* images = (const float*)d_in[0];
    const float* mats   = (const float*)d_in[1];
    float* out = (float*)d_out;

    cudaFuncSetAttribute(warp_resize_kernel,
                         cudaFuncAttributeMaxDynamicSharedMemorySize, DYN_BYTES);

    dim3 grid(OUT_N / TOX, OUT_N / TOY, 32);   // 7 x 28 x 32
    warp_resize_kernel<<<grid, NTHREADS, DYN_BYTES>>>(images, mats, out);
}

// round 7
// speedup vs baseline: 4.1434x; 1.3811x over previous
#include <cuda_runtime.h>
#include <cuda_fp16.h>
#include <cuda_bf16.h>

#define SRC_H 512
#define SRC_W 512
#define NCH   3
#define OUT_N 224
#define TOX   32
#define TOY   8
#define NTAP  6
#define NIX   79
#define NIXP  80
#define NIY   24
#define NTHREADS 256

#define SH_T   48                 // staged rows capacity
#define SW_PX  112                // staged pixels per row (= pitch in px)
#define PITCH_B (SW_PX * 8)       // 896 bytes per staged row (4 halfs/px)
#define ROWF  (SRC_W * NCH)       // 1536 floats per source row
#define IMG3F ((size_t)SRC_H * SRC_W * NCH)
#define TOTF  ((size_t)32 * IMG3F)

// dynamic smem layout (bytes)
#define SZ_SRC  (SH_T * PITCH_B)          // 43008
#define OFF_WRG (SZ_SRC)
#define SZ_WRG  (NIY * NIXP * 4)          // 7680 (half2 RG)
#define OFF_WB  (OFF_WRG + SZ_WRG)
#define SZ_WB   (NIY * NIXP * 2)          // 3840 (half B)
#define OFF_TRG (OFF_WB + SZ_WB)
#define SZ_TRG  (NIY * TOX * 8)           // 6144 (float2)
#define OFF_TB  (OFF_TRG + SZ_TRG)
#define SZ_TB   (NIY * TOX * 4)           // 3072 (float)
#define DYN_BYTES (OFF_TB + SZ_TB)        // 63744

__device__ __forceinline__ unsigned h2u(__half2 h) {
    return *reinterpret_cast<unsigned*>(&h);
}
__device__ __forceinline__ __half2 u2h(unsigned u) {
    return *reinterpret_cast<__half2*>(&u);
}

__global__ __launch_bounds__(NTHREADS, 3) void warp_resize_kernel(
    const float* __restrict__ images,   // (32, 512, 512, 3)
    const float* __restrict__ mats,     // (32, 2, 3)
    float* __restrict__ out)            // (32, 224, 224, 3)
{
    extern __shared__ __align__(16) unsigned char dynraw[];
    unsigned char* s_srcb = dynraw;                       // padded px: RG half2 | B half2
    __half2* s_wRG = (__half2*)(dynraw + OFF_WRG);
    __half*  s_wB  = (__half*) (dynraw + OFF_WB);
    float2*  s_tRG = (float2*) (dynraw + OFF_TRG);
    float*   s_tB  = (float*)  (dynraw + OFF_TB);

    __shared__ float s_wx[TOX][NTAP];
    __shared__ float s_wy[TOY][NTAP];
    __shared__ int   s_bx[TOX];
    __shared__ int   s_by[TOY];

    const int b    = blockIdx.z;
    const int ox0  = blockIdx.x * TOX;
    const int oy0  = blockIdx.y * TOY;
    const int tid  = threadIdx.x;
    const int wrp  = tid >> 5;
    const int lane = tid & 31;

    const float INV = 512.0f / 224.0f;
    const float SC  = 224.0f / 512.0f;

    const int IX0 = (int)floorf((ox0 + 0.5f) * INV - 0.5f) - 2;
    const int IY0 = (int)floorf((oy0 + 0.5f) * INV - 0.5f) - 2;

    // ---- Resize weights (normalized triangle kernel, jax semantics) ----
    if (tid < TOX) {
        int j = ox0 + tid;
        float sf = (j + 0.5f) * INV - 0.5f;
        int i0 = (int)floorf(sf) - 2;
        float wv[NTAP];
        float sum = 0.0f;
        #pragma unroll
        for (int k = 0; k < NTAP; k++) {
            int i = i0 + k;
            float w = fmaxf(1.0f - fabsf(sf - (float)i) * SC, 0.0f);
            if (i < 0 || i >= SRC_W) w = 0.0f;
            wv[k] = w; sum += w;
        }
        float inv = 1.0f / sum;
        #pragma unroll
        for (int k = 0; k < NTAP; k++) s_wx[tid][k] = wv[k] * inv;
        s_bx[tid] = i0 - IX0;
    } else if (tid < TOX + TOY) {
        int t = tid - TOX;
        int j = oy0 + t;
        float sf = (j + 0.5f) * INV - 0.5f;
        int i0 = (int)floorf(sf) - 2;
        float wv[NTAP];
        float sum = 0.0f;
        #pragma unroll
        for (int k = 0; k < NTAP; k++) {
            int i = i0 + k;
            float w = fmaxf(1.0f - fabsf(sf - (float)i) * SC, 0.0f);
            if (i < 0 || i >= SRC_H) w = 0.0f;
            wv[k] = w; sum += w;
        }
        float inv = 1.0f / sum;
        #pragma unroll
        for (int k = 0; k < NTAP; k++) s_wy[t][k] = wv[k] * inv;
        s_by[t] = i0 - IY0;
    }

    const float* Mp = mats + b * 6;
    const float M00 = __ldg(Mp + 0), M01 = __ldg(Mp + 1), M02 = __ldg(Mp + 2);
    const float M10 = __ldg(Mp + 3), M11 = __ldg(Mp + 4), M12 = __ldg(Mp + 5);

    const float* img = images + (size_t)b * IMG3F;

    // ---- Exact affine bbox of the warped tile's source footprint ----
    const float gy0 = (float)IY0, gy1 = (float)(IY0 + NIY - 1);
    const float gx0 = (float)IX0, gx1 = (float)(IX0 + NIX - 1);

    float sy00 = fmaf(M00, gy0, fmaf(M01, gx0, M02));
    float sy01 = fmaf(M00, gy0, fmaf(M01, gx1, M02));
    float sy10 = fmaf(M00, gy1, fmaf(M01, gx0, M02));
    float sy11 = fmaf(M00, gy1, fmaf(M01, gx1, M02));
    float sx00 = fmaf(M10, gy0, fmaf(M11, gx0, M12));
    float sx01 = fmaf(M10, gy0, fmaf(M11, gx1, M12));
    float sx10 = fmaf(M10, gy1, fmaf(M11, gx0, M12));
    float sx11 = fmaf(M10, gy1, fmaf(M11, gx1, M12));

    float symin = fminf(fminf(sy00, sy01), fminf(sy10, sy11));
    float symax = fmaxf(fmaxf(sy00, sy01), fmaxf(sy10, sy11));
    float sxmin = fminf(fminf(sx00, sx01), fminf(sx10, sx11));
    float sxmax = fmaxf(fmaxf(sx00, sx01), fmaxf(sx10, sx11));

    int fy0 = (int)floorf(symin) - 1;
    int fy1 = (int)floorf(symax) + 2;
    int fx0 = (int)floorf(sxmin) - 1;
    int fx1 = (int)floorf(sxmax) + 2;

    bool interior = (fy0 >= 0) && (fy1 < SRC_H) && (fx0 >= 0) && (fx1 < SRC_W);

    int by0 = max(0, fy0);
    int by1 = min(SRC_H - 1, fy1);
    int bx0 = max(0, fx0) & ~3;            // 4-px align for float4 staging
    int bx1 = min(SRC_W - 1, fx1);

    int hgt = by1 - by0 + 1;
    int wid = bx1 - bx0 + 1;
    bool staged = (hgt > 0) && (wid > 0) && (hgt <= SH_T) && (wid <= SW_PX);

    // ---- Stage source box: global fp32 interleaved -> SMEM padded fp16 px ----
    if (staged) {
        size_t base_f = (size_t)b * IMG3F + ((size_t)by0 * SRC_W + bx0) * NCH;
        for (int r = wrp; r < hgt; r += 8) {
            if (lane < 28) {                       // 28 lanes x 4 px = 112 px/row
                size_t fidx = base_f + (size_t)r * ROWF + (size_t)lane * 12;
                float f[12];
                if (fidx + 12 <= TOTF) {
                    const float4* g = (const float4*)(images + fidx);
                    float4 a = g[0], bq = g[1], cq = g[2];
                    f[0]=a.x; f[1]=a.y; f[2]=a.z; f[3]=a.w;
                    f[4]=bq.x; f[5]=bq.y; f[6]=bq.z; f[7]=bq.w;
                    f[8]=cq.x; f[9]=cq.y; f[10]=cq.z; f[11]=cq.w;
                } else {
                    #pragma unroll
                    for (int k = 0; k < 12; k++)
                        f[k] = (fidx + k < TOTF) ? images[fidx + k] : 0.0f;
                }
                uint4 o0, o1;
                o0.x = h2u(__floats2half2_rn(f[0],  f[1]));
                o0.y = h2u(__floats2half2_rn(f[2],  f[2]));
                o0.z = h2u(__floats2half2_rn(f[3],  f[4]));
                o0.w = h2u(__floats2half2_rn(f[5],  f[5]));
                o1.x = h2u(__floats2half2_rn(f[6],  f[7]));
                o1.y = h2u(__floats2half2_rn(f[8],  f[8]));
                o1.z = h2u(__floats2half2_rn(f[9],  f[10]));
                o1.w = h2u(__floats2half2_rn(f[11], f[11]));
                uint4* d = (uint4*)(s_srcb + r * PITCH_B + lane * 32);
                d[0] = o0;
                d[1] = o1;
            }
        }
    }
    __syncthreads();

    // ---- Stage 1: warped tile ----
    const float by0f = (float)by0;
    const float bx0f = (float)bx0;

    for (int ty = wrp; ty < NIY; ty += 8) {
        float gy = (float)(IY0 + ty);
        float sybA = fmaf(M00, gy, M02);               // absolute bases
        float sxbA = fmaf(M10, gy, M12);

        if (staged && interior) {
            float sybR = sybA - by0f;                  // relative bases
            float sxbR = sxbA - bx0f;
            #pragma unroll
            for (int c = 0; c < 3; c++) {
                int tx = c * 32 + lane;
                if (tx < NIX) {
                    float gx = (float)(IX0 + tx);
                    float syr = fmaf(M01, gx, sybR);
                    float sxr = fmaf(M11, gx, sxbR);
                    float fy = floorf(syr), fxx = floorf(sxr);
                    float ay = syr - fy,   ax = sxr - fxx;
                    int iy = (int)fy, ix = (int)fxx;

                    const unsigned char* p = s_srcb + iy * PITCH_B + ix * 8;
                    uint2 q00 = *(const uint2*)(p);
                    uint2 q01 = *(const uint2*)(p + 8);
                    uint2 q10 = *(const uint2*)(p + PITCH_B);
                    uint2 q11 = *(const uint2*)(p + PITCH_B + 8);

                    float oy_ = 1.0f - ay, oxx = 1.0f - ax;
                    __half2 h00 = __float2half2_rn(oy_ * oxx);
                    __half2 h01 = __float2half2_rn(oy_ * ax);
                    __half2 h10 = __float2half2_rn(ay * oxx);
                    __half2 h11 = __float2half2_rn(ay * ax);

                    __half2 aRG = __hmul2(h00, u2h(q00.x));
                    __half2 aBP = __hmul2(h00, u2h(q00.y));
                    aRG = __hfma2(h01, u2h(q01.x), aRG);
                    aBP = __hfma2(h01, u2h(q01.y), aBP);
                    aRG = __hfma2(h10, u2h(q10.x), aRG);
                    aBP = __hfma2(h10, u2h(q10.y), aBP);
                    aRG = __hfma2(h11, u2h(q11.x), aRG);
                    aBP = __hfma2(h11, u2h(q11.y), aBP);

                    s_wRG[ty * NIXP + tx] = aRG;
                    s_wB [ty * NIXP + tx] = __low2half(aBP);
                }
            }
        } else if (staged) {
            // border tile: validity-zeroed weights + clamped in-box indices
            #pragma unroll
            for (int c = 0; c < 3; c++) {
                int tx = c * 32 + lane;
                if (tx < NIX) {
                    float gx = (float)(IX0 + tx);
                    float sy = fmaf(M01, gx, sybA);
                    float sx = fmaf(M11, gx, sxbA);
                    float fy = floorf(sy), fxx = floorf(sx);
                    float ay = sy - fy,   ax = sx - fxx;
                    int iy = (int)fy, ix = (int)fxx;
                    int iy1 = iy + 1, ix1 = ix + 1;

                    float wy0 = ((unsigned)iy  < (unsigned)SRC_H) ? (1.0f - ay) : 0.0f;
                    float wy1 = ((unsigned)iy1 < (unsigned)SRC_H) ? ay : 0.0f;
                    float wx0v = ((unsigned)ix  < (unsigned)SRC_W) ? (1.0f - ax) : 0.0f;
                    float wx1v = ((unsigned)ix1 < (unsigned)SRC_W) ? ax : 0.0f;

                    __half2 h00 = __float2half2_rn(wy0 * wx0v);
                    __half2 h01 = __float2half2_rn(wy0 * wx1v);
                    __half2 h10 = __float2half2_rn(wy1 * wx0v);
                    __half2 h11 = __float2half2_rn(wy1 * wx1v);

                    int ry0 = min(max(iy  - by0, 0), hgt - 1);
                    int ry1 = min(max(iy1 - by0, 0), hgt - 1);
                    int rx0 = min(max(ix  - bx0, 0), wid - 1);
                    int rx1 = min(max(ix1 - bx0, 0), wid - 1);

                    const unsigned char* pA = s_srcb + ry0 * PITCH_B;
                    const unsigned char* pB = s_srcb + ry1 * PITCH_B;
                    uint2 q00 = *(const uint2*)(pA + rx0 * 8);
                    uint2 q01 = *(const uint2*)(pA + rx1 * 8);
                    uint2 q10 = *(const uint2*)(pB + rx0 * 8);
                    uint2 q11 = *(const uint2*)(pB + rx1 * 8);

                    __half2 aRG = __hmul2(h00, u2h(q00.x));
                    __half2 aBP = __hmul2(h00, u2h(q00.y));
                    aRG = __hfma2(h01, u2h(q01.x), aRG);
                    aBP = __hfma2(h01, u2h(q01.y), aBP);
                    aRG = __hfma2(h10, u2h(q10.x), aRG);
                    aBP = __hfma2(h10, u2h(q10.y), aBP);
                    aRG = __hfma2(h11, u2h(q11.x), aRG);
                    aBP = __hfma2(h11, u2h(q11.y), aBP);

                    s_wRG[ty * NIXP + tx] = aRG;
                    s_wB [ty * NIXP + tx] = __low2half(aBP);
                }
            }
        } else {
            // fallback: global fp32 gather (correctness safety net)
            #pragma unroll
            for (int c = 0; c < 3; c++) {
                int tx = c * 32 + lane;
                if (tx < NIX) {
                    float gx = (float)(IX0 + tx);
                    float sy = fmaf(M01, gx, sybA);
                    float sx = fmaf(M11, gx, sxbA);
                    float fy = floorf(sy), fxx = floorf(sx);
                    float ay = sy - fy,   ax = sx - fxx;
                    int iy = (int)fy, ix = (int)fxx;
                    int iy1 = iy + 1, ix1 = ix + 1;

                    float wy0 = ((unsigned)iy  < (unsigned)SRC_H) ? (1.0f - ay) : 0.0f;
                    float wy1 = ((unsigned)iy1 < (unsigned)SRC_H) ? ay : 0.0f;
                    float wx0v = ((unsigned)ix  < (unsigned)SRC_W) ? (1.0f - ax) : 0.0f;
                    float wx1v = ((unsigned)ix1 < (unsigned)SRC_W) ? ax : 0.0f;
                    float w00 = wy0 * wx0v, w01 = wy0 * wx1v;
                    float w10 = wy1 * wx0v, w11 = wy1 * wx1v;

                    int cy0 = min(max(iy, 0), SRC_H - 1);
                    int cy1 = min(max(iy1, 0), SRC_H - 1);
                    int cx0 = min(max(ix, 0), SRC_W - 1);
                    int cx1 = min(max(ix1, 0), SRC_W - 1);
                    const float* p00 = img + ((size_t)cy0 * SRC_W + cx0) * NCH;
                    const float* p01 = img + ((size_t)cy0 * SRC_W + cx1) * NCH;
                    const float* p10 = img + ((size_t)cy1 * SRC_W + cx0) * NCH;
                    const float* p11 = img + ((size_t)cy1 * SRC_W + cx1) * NCH;
                    float r  = w00 * p00[0] + w01 * p01[0] + w10 * p10[0] + w11 * p11[0];
                    float g  = w00 * p00[1] + w01 * p01[1] + w10 * p10[1] + w11 * p11[1];
                    float bl = w00 * p00[2] + w01 * p01[2] + w10 * p10[2] + w11 * p11[2];

                    s_wRG[ty * NIXP + tx] = __floats2half2_rn(r, g);
                    s_wB [ty * NIXP + tx] = __float2half_rn(bl);
                }
            }
        }
    }
    __syncthreads();

    // ---- Stage 2: x-convolution (6 taps, fp32 accum, hoisted weights) ----
    {
        int ox  = tid & 31;
        int tyb = tid >> 5;
        int base = s_bx[ox];
        float w0 = s_wx[ox][0], w1 = s_wx[ox][1], w2 = s_wx[ox][2];
        float w3 = s_wx[ox][3], w4 = s_wx[ox][4], w5 = s_wx[ox][5];
        #pragma unroll
        for (int t = 0; t < 3; t++) {
            int ty = tyb + t * 8;
            const __half2* rowRG = s_wRG + ty * NIXP + base;
            const __half*  rowB  = s_wB  + ty * NIXP + base;
            float a0 = 0.0f, a1 = 0.0f, a2 = 0.0f;
            #pragma unroll
            for (int k = 0; k < NTAP; k++) {
                float w = (k == 0) ? w0 : (k == 1) ? w1 : (k == 2) ? w2
                        : (k == 3) ? w3 : (k == 4) ? w4 : w5;
                float2 f = __half22float2(rowRG[k]);
                a0 = fmaf(w, f.x, a0);
                a1 = fmaf(w, f.y, a1);
                a2 = fmaf(w, __half2float(rowB[k]), a2);
            }
            s_tRG[ty * TOX + ox] = make_float2(a0, a1);
            s_tB [ty * TOX + ox] = a2;
        }
    }
    __syncthreads();

    // ---- Stage 3: y-convolution (6 taps) + store ----
    {
        int oy = tid >> 5;
        int ox = tid & 31;
        int base = s_by[oy];
        float a0 = 0.0f, a1 = 0.0f, a2 = 0.0f;
        #pragma unroll
        for (int k = 0; k < NTAP; k++) {
            float w = s_wy[oy][k];
            float2 f = s_tRG[(base + k) * TOX + ox];
            a0 = fmaf(w, f.x, a0);
            a1 = fmaf(w, f.y, a1);
            a2 = fmaf(w, s_tB[(base + k) * TOX + ox], a2);
        }
        float* op = out + (((size_t)b * OUT_N + (oy0 + oy)) * OUT_N + (ox0 + ox)) * NCH;
        op[0] = a0;
        op[1] = a1;
        op[2] = a2;
    }
}

extern "C" void kernel_launch(void* const* d_in, const int* in_sizes, int n_in,
                              void* d_out, int out_size)
{
    const float* images = (const float*)d_in[0];
    const float* mats   = (const float*)d_in[1];
    float* out = (float*)d_out;

    cudaFuncSetAttribute(warp_resize_kernel,
                         cudaFuncAttributeMaxDynamicSharedMemorySize, DYN_BYTES);

    dim3 grid(OUT_N / TOX, OUT_N / TOY, 32);   // 7 x 28 x 32
    warp_resize_kernel<<<grid, NTHREADS, DYN_BYTES>>>(images, mats, out);
}

// round 8
// speedup vs baseline: 4.4511x; 1.0742x over previous
#include <cuda_runtime.h>
#include <cuda_fp16.h>
#include <cuda_bf16.h>

#define SRC_H 512
#define SRC_W 512
#define NCH   3
#define OUT_N 224
#define TOX   32
#define TOY   8
#define NTAP  6
#define NIX   79
#define NIXP  80
#define NIY   24
#define NTHREADS 256

#define SH_T   48                 // staged rows capacity
#define SW_PX  100                // staged pixels per row
#define PITCH_B (SW_PX * 8)       // 800 bytes per staged row (4 halfs/px)
#define ROWF  (SRC_W * NCH)       // 1536 floats per source row
#define IMG3F ((size_t)SRC_H * SRC_W * NCH)
#define TOTF  ((size_t)32 * IMG3F)

// dynamic smem layout (bytes)
#define SZ_SRC  (SH_T * PITCH_B)          // 38400
#define OFF_WRG (SZ_SRC)
#define SZ_WRG  (NIY * NIXP * 4)          // 7680 (half2 RG)
#define OFF_WB  (OFF_WRG + SZ_WRG)
#define SZ_WB   (NIY * NIXP * 2)          // 3840 (half B)
#define OFF_TRG (OFF_WB + SZ_WB)
#define SZ_TRG  (NIY * TOX * 4)           // 3072 (half2 RG)
#define OFF_TB  (OFF_TRG + SZ_TRG)
#define SZ_TB   (NIY * TOX * 2)           // 1536 (half B)
#define DYN_BYTES (OFF_TB + SZ_TB)        // 54528

__device__ __forceinline__ unsigned h2u(__half2 h) {
    return *reinterpret_cast<unsigned*>(&h);
}
__device__ __forceinline__ __half2 u2h(unsigned u) {
    return *reinterpret_cast<__half2*>(&u);
}

__global__ __launch_bounds__(NTHREADS, 4) void warp_resize_kernel(
    const float* __restrict__ images,   // (32, 512, 512, 3)
    const float* __restrict__ mats,     // (32, 2, 3)
    float* __restrict__ out)            // (32, 224, 224, 3)
{
    extern __shared__ __align__(16) unsigned char dynraw[];
    unsigned char* s_srcb = dynraw;                       // padded px: RG half2 | B half2
    __half2* s_wRG = (__half2*)(dynraw + OFF_WRG);
    __half*  s_wB  = (__half*) (dynraw + OFF_WB);
    __half2* s_tRG = (__half2*)(dynraw + OFF_TRG);
    __half*  s_tB  = (__half*) (dynraw + OFF_TB);

    __shared__ float s_wx[TOX][NTAP];
    __shared__ float s_wy[TOY][NTAP];
    __shared__ int   s_bx[TOX];
    __shared__ int   s_by[TOY];

    const int b    = blockIdx.z;
    const int ox0  = blockIdx.x * TOX;
    const int oy0  = blockIdx.y * TOY;
    const int tid  = threadIdx.x;
    const int wrp  = tid >> 5;
    const int lane = tid & 31;

    const float INV = 512.0f / 224.0f;
    const float SC  = 224.0f / 512.0f;

    const int IX0 = (int)floorf((ox0 + 0.5f) * INV - 0.5f) - 2;
    const int IY0 = (int)floorf((oy0 + 0.5f) * INV - 0.5f) - 2;

    // ---- Resize weights (normalized triangle kernel, jax semantics) ----
    if (tid < TOX) {
        int j = ox0 + tid;
        float sf = (j + 0.5f) * INV - 0.5f;
        int i0 = (int)floorf(sf) - 2;
        float wv[NTAP];
        float sum = 0.0f;
        #pragma unroll
        for (int k = 0; k < NTAP; k++) {
            int i = i0 + k;
            float w = fmaxf(1.0f - fabsf(sf - (float)i) * SC, 0.0f);
            if (i < 0 || i >= SRC_W) w = 0.0f;
            wv[k] = w; sum += w;
        }
        float inv = 1.0f / sum;
        #pragma unroll
        for (int k = 0; k < NTAP; k++) s_wx[tid][k] = wv[k] * inv;
        s_bx[tid] = i0 - IX0;
    } else if (tid < TOX + TOY) {
        int t = tid - TOX;
        int j = oy0 + t;
        float sf = (j + 0.5f) * INV - 0.5f;
        int i0 = (int)floorf(sf) - 2;
        float wv[NTAP];
        float sum = 0.0f;
        #pragma unroll
        for (int k = 0; k < NTAP; k++) {
            int i = i0 + k;
            float w = fmaxf(1.0f - fabsf(sf - (float)i) * SC, 0.0f);
            if (i < 0 || i >= SRC_H) w = 0.0f;
            wv[k] = w; sum += w;
        }
        float inv = 1.0f / sum;
        #pragma unroll
        for (int k = 0; k < NTAP; k++) s_wy[t][k] = wv[k] * inv;
        s_by[t] = i0 - IY0;
    }

    const float* Mp = mats + b * 6;
    const float M00 = __ldg(Mp + 0), M01 = __ldg(Mp + 1), M02 = __ldg(Mp + 2);
    const float M10 = __ldg(Mp + 3), M11 = __ldg(Mp + 4), M12 = __ldg(Mp + 5);

    const float* img = images + (size_t)b * IMG3F;

    // ---- Exact affine bbox of the warped tile's source footprint ----
    const float gy0 = (float)IY0, gy1 = (float)(IY0 + NIY - 1);
    const float gx0 = (float)IX0, gx1 = (float)(IX0 + NIX - 1);

    float sy00 = fmaf(M00, gy0, fmaf(M01, gx0, M02));
    float sy01 = fmaf(M00, gy0, fmaf(M01, gx1, M02));
    float sy10 = fmaf(M00, gy1, fmaf(M01, gx0, M02));
    float sy11 = fmaf(M00, gy1, fmaf(M01, gx1, M02));
    float sx00 = fmaf(M10, gy0, fmaf(M11, gx0, M12));
    float sx01 = fmaf(M10, gy0, fmaf(M11, gx1, M12));
    float sx10 = fmaf(M10, gy1, fmaf(M11, gx0, M12));
    float sx11 = fmaf(M10, gy1, fmaf(M11, gx1, M12));

    float symin = fminf(fminf(sy00, sy01), fminf(sy10, sy11));
    float symax = fmaxf(fmaxf(sy00, sy01), fmaxf(sy10, sy11));
    float sxmin = fminf(fminf(sx00, sx01), fminf(sx10, sx11));
    float sxmax = fmaxf(fmaxf(sx00, sx01), fmaxf(sx10, sx11));

    int fy0 = (int)floorf(symin) - 1;
    int fy1 = (int)floorf(symax) + 2;
    int fx0 = (int)floorf(sxmin) - 1;
    int fx1 = (int)floorf(sxmax) + 2;

    bool interior = (fy0 >= 0) && (fy1 < SRC_H) && (fx0 >= 0) && (fx1 < SRC_W);

    int by0 = max(0, fy0);
    int by1 = min(SRC_H - 1, fy1);
    int bx0 = max(0, fx0) & ~3;            // 4-px align for float4 staging
    int bx1 = min(SRC_W - 1, fx1);

    int hgt = by1 - by0 + 1;
    int wid = bx1 - bx0 + 1;
    bool staged = (hgt > 0) && (wid > 0) && (hgt <= SH_T) && (wid <= SW_PX);

    // ---- Stage source box: global fp32 interleaved -> SMEM padded fp16 px ----
    if (staged) {
        size_t base_f = (size_t)b * IMG3F + ((size_t)by0 * SRC_W + bx0) * NCH;
        for (int r = wrp; r < hgt; r += 8) {
            if (lane < 25) {                       // 25 lanes x 4 px = 100 px/row
                size_t fidx = base_f + (size_t)r * ROWF + (size_t)lane * 12;
                float f[12];
                if (fidx + 12 <= TOTF) {
                    const float4* g = (const float4*)(images + fidx);
                    float4 a = g[0], bq = g[1], cq = g[2];
                    f[0]=a.x; f[1]=a.y; f[2]=a.z; f[3]=a.w;
                    f[4]=bq.x; f[5]=bq.y; f[6]=bq.z; f[7]=bq.w;
                    f[8]=cq.x; f[9]=cq.y; f[10]=cq.z; f[11]=cq.w;
                } else {
                    #pragma unroll
                    for (int k = 0; k < 12; k++)
                        f[k] = (fidx + k < TOTF) ? images[fidx + k] : 0.0f;
                }
                uint4 o0, o1;
                o0.x = h2u(__floats2half2_rn(f[0],  f[1]));
                o0.y = h2u(__floats2half2_rn(f[2],  f[2]));
                o0.z = h2u(__floats2half2_rn(f[3],  f[4]));
                o0.w = h2u(__floats2half2_rn(f[5],  f[5]));
                o1.x = h2u(__floats2half2_rn(f[6],  f[7]));
                o1.y = h2u(__floats2half2_rn(f[8],  f[8]));
                o1.z = h2u(__floats2half2_rn(f[9],  f[10]));
                o1.w = h2u(__floats2half2_rn(f[11], f[11]));
                uint4* d = (uint4*)(s_srcb + r * PITCH_B + lane * 32);
                d[0] = o0;
                d[1] = o1;
            }
        }
    }
    __syncthreads();

    // ---- Stage 1: warped tile ----
    const float by0f = (float)by0;
    const float bx0f = (float)bx0;

    for (int ty = wrp; ty < NIY; ty += 8) {
        float gy = (float)(IY0 + ty);
        float sybA = fmaf(M00, gy, M02);               // absolute bases
        float sxbA = fmaf(M10, gy, M12);

        if (staged && interior) {
            float sybR = sybA - by0f;                  // relative bases
            float sxbR = sxbA - bx0f;
            #pragma unroll
            for (int c = 0; c < 3; c++) {
                int tx = c * 32 + lane;
                if (tx < NIX) {
                    float gx = (float)(IX0 + tx);
                    float syr = fmaf(M01, gx, sybR);
                    float sxr = fmaf(M11, gx, sxbR);
                    float fy = floorf(syr), fxx = floorf(sxr);
                    float ay = syr - fy,   ax = sxr - fxx;
                    int iy = (int)fy, ix = (int)fxx;

                    const unsigned char* p = s_srcb + iy * PITCH_B + ix * 8;
                    uint2 q00 = *(const uint2*)(p);
                    uint2 q01 = *(const uint2*)(p + 8);
                    uint2 q10 = *(const uint2*)(p + PITCH_B);
                    uint2 q11 = *(const uint2*)(p + PITCH_B + 8);

                    float oy_ = 1.0f - ay, oxx = 1.0f - ax;
                    __half2 h00 = __float2half2_rn(oy_ * oxx);
                    __half2 h01 = __float2half2_rn(oy_ * ax);
                    __half2 h10 = __float2half2_rn(ay * oxx);
                    __half2 h11 = __float2half2_rn(ay * ax);

                    __half2 aRG = __hmul2(h00, u2h(q00.x));
                    __half2 aBP = __hmul2(h00, u2h(q00.y));
                    aRG = __hfma2(h01, u2h(q01.x), aRG);
                    aBP = __hfma2(h01, u2h(q01.y), aBP);
                    aRG = __hfma2(h10, u2h(q10.x), aRG);
                    aBP = __hfma2(h10, u2h(q10.y), aBP);
                    aRG = __hfma2(h11, u2h(q11.x), aRG);
                    aBP = __hfma2(h11, u2h(q11.y), aBP);

                    s_wRG[ty * NIXP + tx] = aRG;
                    s_wB [ty * NIXP + tx] = __low2half(aBP);
                }
            }
        } else if (staged) {
            // border tile: validity-zeroed weights + clamped in-box indices
            #pragma unroll
            for (int c = 0; c < 3; c++) {
                int tx = c * 32 + lane;
                if (tx < NIX) {
                    float gx = (float)(IX0 + tx);
                    float sy = fmaf(M01, gx, sybA);
                    float sx = fmaf(M11, gx, sxbA);
                    float fy = floorf(sy), fxx = floorf(sx);
                    float ay = sy - fy,   ax = sx - fxx;
                    int iy = (int)fy, ix = (int)fxx;
                    int iy1 = iy + 1, ix1 = ix + 1;

                    float wy0 = ((unsigned)iy  < (unsigned)SRC_H) ? (1.0f - ay) : 0.0f;
                    float wy1 = ((unsigned)iy1 < (unsigned)SRC_H) ? ay : 0.0f;
                    float wx0v = ((unsigned)ix  < (unsigned)SRC_W) ? (1.0f - ax) : 0.0f;
                    float wx1v = ((unsigned)ix1 < (unsigned)SRC_W) ? ax : 0.0f;

                    __half2 h00 = __float2half2_rn(wy0 * wx0v);
                    __half2 h01 = __float2half2_rn(wy0 * wx1v);
                    __half2 h10 = __float2half2_rn(wy1 * wx0v);
                    __half2 h11 = __float2half2_rn(wy1 * wx1v);

                    int ry0 = min(max(iy  - by0, 0), hgt - 1);
                    int ry1 = min(max(iy1 - by0, 0), hgt - 1);
                    int rx0 = min(max(ix  - bx0, 0), wid - 1);
                    int rx1 = min(max(ix1 - bx0, 0), wid - 1);

                    const unsigned char* pA = s_srcb + ry0 * PITCH_B;
                    const unsigned char* pB = s_srcb + ry1 * PITCH_B;
                    uint2 q00 = *(const uint2*)(pA + rx0 * 8);
                    uint2 q01 = *(const uint2*)(pA + rx1 * 8);
                    uint2 q10 = *(const uint2*)(pB + rx0 * 8);
                    uint2 q11 = *(const uint2*)(pB + rx1 * 8);

                    __half2 aRG = __hmul2(h00, u2h(q00.x));
                    __half2 aBP = __hmul2(h00, u2h(q00.y));
                    aRG = __hfma2(h01, u2h(q01.x), aRG);
                    aBP = __hfma2(h01, u2h(q01.y), aBP);
                    aRG = __hfma2(h10, u2h(q10.x), aRG);
                    aBP = __hfma2(h10, u2h(q10.y), aBP);
                    aRG = __hfma2(h11, u2h(q11.x), aRG);
                    aBP = __hfma2(h11, u2h(q11.y), aBP);

                    s_wRG[ty * NIXP + tx] = aRG;
                    s_wB [ty * NIXP + tx] = __low2half(aBP);
                }
            }
        } else {
            // fallback: global fp32 gather (correctness safety net)
            #pragma unroll 1
            for (int c = 0; c < 3; c++) {
                int tx = c * 32 + lane;
                if (tx < NIX) {
                    float gx = (float)(IX0 + tx);
                    float sy = fmaf(M01, gx, sybA);
                    float sx = fmaf(M11, gx, sxbA);
                    float fy = floorf(sy), fxx = floorf(sx);
                    float ay = sy - fy,   ax = sx - fxx;
                    int iy = (int)fy, ix = (int)fxx;
                    int iy1 = iy + 1, ix1 = ix + 1;

                    float wy0 = ((unsigned)iy  < (unsigned)SRC_H) ? (1.0f - ay) : 0.0f;
                    float wy1 = ((unsigned)iy1 < (unsigned)SRC_H) ? ay : 0.0f;
                    float wx0v = ((unsigned)ix  < (unsigned)SRC_W) ? (1.0f - ax) : 0.0f;
                    float wx1v = ((unsigned)ix1 < (unsigned)SRC_W) ? ax : 0.0f;
                    float w00 = wy0 * wx0v, w01 = wy0 * wx1v;
                    float w10 = wy1 * wx0v, w11 = wy1 * wx1v;

                    int cy0 = min(max(iy, 0), SRC_H - 1);
                    int cy1 = min(max(iy1, 0), SRC_H - 1);
                    int cx0 = min(max(ix, 0), SRC_W - 1);
                    int cx1 = min(max(ix1, 0), SRC_W - 1);
                    const float* p00 = img + ((size_t)cy0 * SRC_W + cx0) * NCH;
                    const float* p01 = img + ((size_t)cy0 * SRC_W + cx1) * NCH;
                    const float* p10 = img + ((size_t)cy1 * SRC_W + cx0) * NCH;
                    const float* p11 = img + ((size_t)cy1 * SRC_W + cx1) * NCH;
                    float r  = w00 * p00[0] + w01 * p01[0] + w10 * p10[0] + w11 * p11[0];
                    float g  = w00 * p00[1] + w01 * p01[1] + w10 * p10[1] + w11 * p11[1];
                    float bl = w00 * p00[2] + w01 * p01[2] + w10 * p10[2] + w11 * p11[2];

                    s_wRG[ty * NIXP + tx] = __floats2half2_rn(r, g);
                    s_wB [ty * NIXP + tx] = __float2half_rn(bl);
                }
            }
        }
    }
    __syncthreads();

    // ---- Stage 2: x-convolution (6 taps, fp32 accum, hoisted weights) ----
    {
        int ox  = tid & 31;
        int tyb = tid >> 5;
        int base = s_bx[ox];
        float w0 = s_wx[ox][0], w1 = s_wx[ox][1], w2 = s_wx[ox][2];
        float w3 = s_wx[ox][3], w4 = s_wx[ox][4], w5 = s_wx[ox][5];
        #pragma unroll
        for (int t = 0; t < 3; t++) {
            int ty = tyb + t * 8;
            const __half2* rowRG = s_wRG + ty * NIXP + base;
            const __half*  rowB  = s_wB  + ty * NIXP + base;
            float a0 = 0.0f, a1 = 0.0f, a2 = 0.0f;
            #pragma unroll
            for (int k = 0; k < NTAP; k++) {
                float w = (k == 0) ? w0 : (k == 1) ? w1 : (k == 2) ? w2
                        : (k == 3) ? w3 : (k == 4) ? w4 : w5;
                float2 f = __half22float2(rowRG[k]);
                a0 = fmaf(w, f.x, a0);
                a1 = fmaf(w, f.y, a1);
                a2 = fmaf(w, __half2float(rowB[k]), a2);
            }
            s_tRG[ty * TOX + ox] = __floats2half2_rn(a0, a1);
            s_tB [ty * TOX + ox] = __float2half_rn(a2);
        }
    }
    __syncthreads();

    // ---- Stage 3: y-convolution (6 taps) + store ----
    {
        int oy = tid >> 5;
        int ox = tid & 31;
        int base = s_by[oy];
        float a0 = 0.0f, a1 = 0.0f, a2 = 0.0f;
        #pragma unroll
        for (int k = 0; k < NTAP; k++) {
            float w = s_wy[oy][k];
            float2 f = __half22float2(s_tRG[(base + k) * TOX + ox]);
            a0 = fmaf(w, f.x, a0);
            a1 = fmaf(w, f.y, a1);
            a2 = fmaf(w, __half2float(s_tB[(base + k) * TOX + ox]), a2);
        }
        float* op = out + (((size_t)b * OUT_N + (oy0 + oy)) * OUT_N + (ox0 + ox)) * NCH;
        op[0] = a0;
        op[1] = a1;
        op[2] = a2;
    }
}

extern "C" void kernel_launch(void* const* d_in, const int* in_sizes, int n_in,
                              void* d_out, int out_size)
{
    const float* images = (const float*)d_in[0];
    const float* mats   = (const float*)d_in[1];
    float* out = (float*)d_out;

    cudaFuncSetAttribute(warp_resize_kernel,
                         cudaFuncAttributeMaxDynamicSharedMemorySize, DYN_BYTES);

    dim3 grid(OUT_N / TOX, OUT_N / TOY, 32);   // 7 x 28 x 32
    warp_resize_kernel<<<grid, NTHREADS, DYN_BYTES>>>(images, mats, out);
}

// round 9
// speedup vs baseline: 4.7969x; 1.0777x over previous
#include <cuda_runtime.h>
#include <cuda_fp16.h>
#include <cuda_bf16.h>

#define SRC_H 512
#define SRC_W 512
#define NCH   3
#define OUT_N 224
#define TOX   32
#define TOY   8
#define NTAP  6
#define NIX   79
#define NIY   24
#define WPITCH 82                 // skewed s_w pitch (79 + 2 skew + pad)
#define NTHREADS 256

#define SH_T   48                 // staged rows capacity
#define SW_PX  100                // staged pixels per row
#define ROWF  (SRC_W * NCH)
#define IMG3F ((size_t)SRC_H * SRC_W * NCH)
#define TOTF  ((size_t)32 * IMG3F)

// dynamic smem layout (bytes)
#define OFF_SRG 0
#define SZ_SRG  (SH_T * SW_PX * 4)        // 19200  RG plane (half2/px)
#define OFF_SB  (OFF_SRG + SZ_SRG)
#define SZ_SB   (SH_T * SW_PX * 2)        // 9600   B plane (half/px)
#define OFF_WRG (OFF_SB + SZ_SB)          // 28800
#define SZ_WRG  (NIY * WPITCH * 4)        // 7872
#define OFF_WB  (OFF_WRG + SZ_WRG)
#define SZ_WB   (NIY * WPITCH * 2)        // 3936
#define DYN_BYTES (OFF_WB + SZ_WB)        // 40608
// s_t aliases the staging region (dead after stage 1): 9216 B <= 28800 B
#define OFF_TRG 0
#define OFF_TB  (NIY * TOX * 8)           // 6144

__device__ __forceinline__ unsigned h2u(__half2 h) {
    return *reinterpret_cast<unsigned*>(&h);
}

__global__ __launch_bounds__(NTHREADS, 5) void warp_resize_kernel(
    const float* __restrict__ images,   // (32, 512, 512, 3)
    const float* __restrict__ mats,     // (32, 2, 3)
    float* __restrict__ out)            // (32, 224, 224, 3)
{
    extern __shared__ __align__(16) unsigned char dynraw[];
    __half2* s_RG  = (__half2*)(dynraw + OFF_SRG);     // staged RG plane, pitch SW_PX
    __half*  s_B   = (__half*) (dynraw + OFF_SB);      // staged B plane, pitch SW_PX
    __half2* s_wRG = (__half2*)(dynraw + OFF_WRG);     // warped RG, skewed pitch
    __half*  s_wB  = (__half*) (dynraw + OFF_WB);      // warped B, skewed pitch
    float2*  s_tRG = (float2*) (dynraw + OFF_TRG);     // aliases staging (stage2+)
    float*   s_tB  = (float*)  (dynraw + OFF_TB);

    __shared__ float s_wx[TOX][NTAP];
    __shared__ float s_wy[TOY][NTAP];
    __shared__ int   s_bx[TOX];
    __shared__ int   s_by[TOY];

    const int b    = blockIdx.z;
    const int ox0  = blockIdx.x * TOX;
    const int oy0  = blockIdx.y * TOY;
    const int tid  = threadIdx.x;
    const int wrp  = tid >> 5;
    const int lane = tid & 31;

    const float INV = 512.0f / 224.0f;
    const float SC  = 224.0f / 512.0f;

    const int IX0 = (int)floorf((ox0 + 0.5f) * INV - 0.5f) - 2;
    const int IY0 = (int)floorf((oy0 + 0.5f) * INV - 0.5f) - 2;

    // ---- Resize weights (normalized triangle kernel, jax semantics) ----
    if (tid < TOX) {
        int j = ox0 + tid;
        float sf = (j + 0.5f) * INV - 0.5f;
        int i0 = (int)floorf(sf) - 2;
        float wv[NTAP];
        float sum = 0.0f;
        #pragma unroll
        for (int k = 0; k < NTAP; k++) {
            int i = i0 + k;
            float w = fmaxf(1.0f - fabsf(sf - (float)i) * SC, 0.0f);
            if (i < 0 || i >= SRC_W) w = 0.0f;
            wv[k] = w; sum += w;
        }
        float inv = 1.0f / sum;
        #pragma unroll
        for (int k = 0; k < NTAP; k++) s_wx[tid][k] = wv[k] * inv;
        s_bx[tid] = i0 - IX0;
    } else if (tid < TOX + TOY) {
        int t = tid - TOX;
        int j = oy0 + t;
        float sf = (j + 0.5f) * INV - 0.5f;
        int i0 = (int)floorf(sf) - 2;
        float wv[NTAP];
        float sum = 0.0f;
        #pragma unroll
        for (int k = 0; k < NTAP; k++) {
            int i = i0 + k;
            float w = fmaxf(1.0f - fabsf(sf - (float)i) * SC, 0.0f);
            if (i < 0 || i >= SRC_H) w = 0.0f;
            wv[k] = w; sum += w;
        }
        float inv = 1.0f / sum;
        #pragma unroll
        for (int k = 0; k < NTAP; k++) s_wy[t][k] = wv[k] * inv;
        s_by[t] = i0 - IY0;
    }

    const float* Mp = mats + b * 6;
    const float M00 = __ldg(Mp + 0), M01 = __ldg(Mp + 1), M02 = __ldg(Mp + 2);
    const float M10 = __ldg(Mp + 3), M11 = __ldg(Mp + 4), M12 = __ldg(Mp + 5);

    const float* img = images + (size_t)b * IMG3F;

    // ---- Exact affine bbox of the warped tile's source footprint ----
    const float gy0 = (float)IY0, gy1 = (float)(IY0 + NIY - 1);
    const float gx0 = (float)IX0, gx1 = (float)(IX0 + NIX - 1);

    float sy00 = fmaf(M00, gy0, fmaf(M01, gx0, M02));
    float sy01 = fmaf(M00, gy0, fmaf(M01, gx1, M02));
    float sy10 = fmaf(M00, gy1, fmaf(M01, gx0, M02));
    float sy11 = fmaf(M00, gy1, fmaf(M01, gx1, M02));
    float sx00 = fmaf(M10, gy0, fmaf(M11, gx0, M12));
    float sx01 = fmaf(M10, gy0, fmaf(M11, gx1, M12));
    float sx10 = fmaf(M10, gy1, fmaf(M11, gx0, M12));
    float sx11 = fmaf(M10, gy1, fmaf(M11, gx1, M12));

    float symin = fminf(fminf(sy00, sy01), fminf(sy10, sy11));
    float symax = fmaxf(fmaxf(sy00, sy01), fmaxf(sy10, sy11));
    float sxmin = fminf(fminf(sx00, sx01), fminf(sx10, sx11));
    float sxmax = fmaxf(fmaxf(sx00, sx01), fmaxf(sx10, sx11));

    int fy0 = (int)floorf(symin) - 1;
    int fy1 = (int)floorf(symax) + 2;
    int fx0 = (int)floorf(sxmin) - 1;
    int fx1 = (int)floorf(sxmax) + 2;

    bool interior = (fy0 >= 0) && (fy1 < SRC_H) && (fx0 >= 0) && (fx1 < SRC_W);

    int by0 = max(0, fy0);
    int by1 = min(SRC_H - 1, fy1);
    int bx0 = max(0, fx0) & ~3;            // 4-px align for float4 staging
    int bx1 = min(SRC_W - 1, fx1);

    int hgt = by1 - by0 + 1;
    int wid = bx1 - bx0 + 1;
    bool staged = (hgt > 0) && (wid > 0) && (hgt <= SH_T) && (wid <= SW_PX);

    // ---- Stage source box: fp32 interleaved -> SMEM planar fp16 (RG half2 + B half) ----
    if (staged) {
        size_t base_f = (size_t)b * IMG3F + ((size_t)by0 * SRC_W + bx0) * NCH;
        for (int r = wrp; r < hgt; r += 8) {
            if (lane < 25) {                       // 25 lanes x 4 px = 100 px/row
                size_t fidx = base_f + (size_t)r * ROWF + (size_t)lane * 12;
                float f[12];
                if (fidx + 12 <= TOTF) {
                    const float4* g = (const float4*)(images + fidx);
                    float4 a = g[0], bq = g[1], cq = g[2];
                    f[0]=a.x; f[1]=a.y; f[2]=a.z; f[3]=a.w;
                    f[4]=bq.x; f[5]=bq.y; f[6]=bq.z; f[7]=bq.w;
                    f[8]=cq.x; f[9]=cq.y; f[10]=cq.z; f[11]=cq.w;
                } else {
                    #pragma unroll
                    for (int k = 0; k < 12; k++)
                        f[k] = (fidx + k < TOTF) ? images[fidx + k] : 0.0f;
                }
                uint4 rg;
                rg.x = h2u(__floats2half2_rn(f[0], f[1]));
                rg.y = h2u(__floats2half2_rn(f[3], f[4]));
                rg.z = h2u(__floats2half2_rn(f[6], f[7]));
                rg.w = h2u(__floats2half2_rn(f[9], f[10]));
                uint2 bb;
                bb.x = h2u(__floats2half2_rn(f[2], f[5]));
                bb.y = h2u(__floats2half2_rn(f[8], f[11]));
                *(uint4*)(s_RG + r * SW_PX + lane * 4) = rg;
                *(uint2*)(s_B  + r * SW_PX + lane * 4) = bb;
            }
        }
    }
    __syncthreads();

    // ---- Stage 1: warped tile ----
    const float by0f = (float)by0;
    const float bx0f = (float)bx0;

    for (int ty = wrp; ty < NIY; ty += 8) {
        float gy = (float)(IY0 + ty);
        float sybA = fmaf(M00, gy, M02);               // absolute bases
        float sxbA = fmaf(M10, gy, M12);

        if (staged && interior) {
            float sybR = sybA - by0f;
            float sxbR = sxbA - bx0f;
            #pragma unroll
            for (int c = 0; c < 3; c++) {
                int tx = c * 32 + lane;
                if (tx < NIX) {
                    float gx = (float)(IX0 + tx);
                    float syr = fmaf(M01, gx, sybR);
                    float sxr = fmaf(M11, gx, sxbR);
                    float fy = floorf(syr), fxx = floorf(sxr);
                    float ay = syr - fy,   ax = sxr - fxx;
                    int iy = (int)fy, ix = (int)fxx;

                    float oy_ = 1.0f - ay, oxx = 1.0f - ax;
                    float w00 = oy_ * oxx, w01 = oy_ * ax;
                    float w10 = ay * oxx,  w11 = ay * ax;

                    const __half2* r0 = s_RG + iy * SW_PX + ix;
                    __half2 q00 = r0[0], q01 = r0[1];
                    __half2 q10 = r0[SW_PX], q11 = r0[SW_PX + 1];
                    const __half* rb = s_B + iy * SW_PX + ix;
                    float b00 = __half2float(rb[0]);
                    float b01 = __half2float(rb[1]);
                    float b10 = __half2float(rb[SW_PX]);
                    float b11 = __half2float(rb[SW_PX + 1]);

                    __half2 aRG = __hmul2(__float2half2_rn(w00), q00);
                    aRG = __hfma2(__float2half2_rn(w01), q01, aRG);
                    aRG = __hfma2(__float2half2_rn(w10), q10, aRG);
                    aRG = __hfma2(__float2half2_rn(w11), q11, aRG);
                    float bl = w00 * b00 + w01 * b01 + w10 * b10 + w11 * b11;

                    int idx = tx + (tx >> 5);
                    s_wRG[ty * WPITCH + idx] = aRG;
                    s_wB [ty * WPITCH + idx] = __float2half_rn(bl);
                }
            }
        } else if (staged) {
            // border tile: validity-zeroed weights + clamped in-box indices
            #pragma unroll
            for (int c = 0; c < 3; c++) {
                int tx = c * 32 + lane;
                if (tx < NIX) {
                    float gx = (float)(IX0 + tx);
                    float sy = fmaf(M01, gx, sybA);
                    float sx = fmaf(M11, gx, sxbA);
                    float fy = floorf(sy), fxx = floorf(sx);
                    float ay = sy - fy,   ax = sx - fxx;
                    int iy = (int)fy, ix = (int)fxx;
                    int iy1 = iy + 1, ix1 = ix + 1;

                    float wy0 = ((unsigned)iy  < (unsigned)SRC_H) ? (1.0f - ay) : 0.0f;
                    float wy1 = ((unsigned)iy1 < (unsigned)SRC_H) ? ay : 0.0f;
                    float wx0v = ((unsigned)ix  < (unsigned)SRC_W) ? (1.0f - ax) : 0.0f;
                    float wx1v = ((unsigned)ix1 < (unsigned)SRC_W) ? ax : 0.0f;
                    float w00 = wy0 * wx0v, w01 = wy0 * wx1v;
                    float w10 = wy1 * wx0v, w11 = wy1 * wx1v;

                    int ry0 = min(max(iy  - by0, 0), hgt - 1);
                    int ry1 = min(max(iy1 - by0, 0), hgt - 1);
                    int rx0 = min(max(ix  - bx0, 0), wid - 1);
                    int rx1 = min(max(ix1 - bx0, 0), wid - 1);

                    __half2 q00 = s_RG[ry0 * SW_PX + rx0];
                    __half2 q01 = s_RG[ry0 * SW_PX + rx1];
                    __half2 q10 = s_RG[ry1 * SW_PX + rx0];
                    __half2 q11 = s_RG[ry1 * SW_PX + rx1];
                    float b00 = __half2float(s_B[ry0 * SW_PX + rx0]);
                    float b01 = __half2float(s_B[ry0 * SW_PX + rx1]);
                    float b10 = __half2float(s_B[ry1 * SW_PX + rx0]);
                    float b11 = __half2float(s_B[ry1 * SW_PX + rx1]);

                    __half2 aRG = __hmul2(__float2half2_rn(w00), q00);
                    aRG = __hfma2(__float2half2_rn(w01), q01, aRG);
                    aRG = __hfma2(__float2half2_rn(w10), q10, aRG);
                    aRG = __hfma2(__float2half2_rn(w11), q11, aRG);
                    float bl = w00 * b00 + w01 * b01 + w10 * b10 + w11 * b11;

                    int idx = tx + (tx >> 5);
                    s_wRG[ty * WPITCH + idx] = aRG;
                    s_wB [ty * WPITCH + idx] = __float2half_rn(bl);
                }
            }
        } else {
            // fallback: global fp32 gather (correctness safety net)
            #pragma unroll 1
            for (int c = 0; c < 3; c++) {
                int tx = c * 32 + lane;
                if (tx < NIX) {
                    float gx = (float)(IX0 + tx);
                    float sy = fmaf(M01, gx, sybA);
                    float sx = fmaf(M11, gx, sxbA);
                    float fy = floorf(sy), fxx = floorf(sx);
                    float ay = sy - fy,   ax = sx - fxx;
                    int iy = (int)fy, ix = (int)fxx;
                    int iy1 = iy + 1, ix1 = ix + 1;

                    float wy0 = ((unsigned)iy  < (unsigned)SRC_H) ? (1.0f - ay) : 0.0f;
                    float wy1 = ((unsigned)iy1 < (unsigned)SRC_H) ? ay : 0.0f;
                    float wx0v = ((unsigned)ix  < (unsigned)SRC_W) ? (1.0f - ax) : 0.0f;
                    float wx1v = ((unsigned)ix1 < (unsigned)SRC_W) ? ax : 0.0f;
                    float w00 = wy0 * wx0v, w01 = wy0 * wx1v;
                    float w10 = wy1 * wx0v, w11 = wy1 * wx1v;

                    int cy0 = min(max(iy, 0), SRC_H - 1);
                    int cy1 = min(max(iy1, 0), SRC_H - 1);
                    int cx0 = min(max(ix, 0), SRC_W - 1);
                    int cx1 = min(max(ix1, 0), SRC_W - 1);
                    const float* p00 = img + ((size_t)cy0 * SRC_W + cx0) * NCH;
                    const float* p01 = img + ((size_t)cy0 * SRC_W + cx1) * NCH;
                    const float* p10 = img + ((size_t)cy1 * SRC_W + cx0) * NCH;
                    const float* p11 = img + ((size_t)cy1 * SRC_W + cx1) * NCH;
                    float r  = w00 * p00[0] + w01 * p01[0] + w10 * p10[0] + w11 * p11[0];
                    float g  = w00 * p00[1] + w01 * p01[1] + w10 * p10[1] + w11 * p11[1];
                    float bl = w00 * p00[2] + w01 * p01[2] + w10 * p10[2] + w11 * p11[2];

                    int idx = tx + (tx >> 5);
                    s_wRG[ty * WPITCH + idx] = __floats2half2_rn(r, g);
                    s_wB [ty * WPITCH + idx] = __float2half_rn(bl);
                }
            }
        }
    }
    __syncthreads();

    // ---- Stage 2: x-convolution (6 taps, fp32 accum, skewed reads) ----
    {
        int ox  = tid & 31;
        int tyb = tid >> 5;
        int base = s_bx[ox];
        float w0 = s_wx[ox][0], w1 = s_wx[ox][1], w2 = s_wx[ox][2];
        float w3 = s_wx[ox][3], w4 = s_wx[ox][4], w5 = s_wx[ox][5];
        #pragma unroll
        for (int t = 0; t < 3; t++) {
            int ty = tyb + t * 8;
            const __half2* rowRG = s_wRG + ty * WPITCH;
            const __half*  rowB  = s_wB  + ty * WPITCH;
            float a0 = 0.0f, a1 = 0.0f, a2 = 0.0f;
            #pragma unroll
            for (int k = 0; k < NTAP; k++) {
                float w = (k == 0) ? w0 : (k == 1) ? w1 : (k == 2) ? w2
                        : (k == 3) ? w3 : (k == 4) ? w4 : w5;
                int wdx = base + k;
                int idx = wdx + (wdx >> 5);
                float2 f = __half22float2(rowRG[idx]);
                a0 = fmaf(w, f.x, a0);
                a1 = fmaf(w, f.y, a1);
                a2 = fmaf(w, __half2float(rowB[idx]), a2);
            }
            s_tRG[ty * TOX + ox] = make_float2(a0, a1);
            s_tB [ty * TOX + ox] = a2;
        }
    }
    __syncthreads();

    // ---- Stage 3: y-convolution (6 taps) + store ----
    {
        int oy = tid >> 5;
        int ox = tid & 31;
        int base = s_by[oy];
        float a0 = 0.0f, a1 = 0.0f, a2 = 0.0f;
        #pragma unroll
        for (int k = 0; k < NTAP; k++) {
            float w = s_wy[oy][k];
            float2 f = s_tRG[(base + k) * TOX + ox];
            a0 = fmaf(w, f.x, a0);
            a1 = fmaf(w, f.y, a1);
            a2 = fmaf(w, s_tB[(base + k) * TOX + ox], a2);
        }
        float* op = out + (((size_t)b * OUT_N + (oy0 + oy)) * OUT_N + (ox0 + ox)) * NCH;
        op[0] = a0;
        op[1] = a1;
        op[2] = a2;
    }
}

extern "C" void kernel_launch(void* const* d_in, const int* in_sizes, int n_in,
                              void* d_out, int out_size)
{
    const float* images = (const float*)d_in[0];
    const float* mats   = (const float*)d_in[1];
    float* out = (float*)d_out;

    cudaFuncSetAttribute(warp_resize_kernel,
                         cudaFuncAttributeMaxDynamicSharedMemorySize, DYN_BYTES);

    dim3 grid(OUT_N / TOX, OUT_N / TOY, 32);   // 7 x 28 x 32
    warp_resize_kernel<<<grid, NTHREADS, DYN_BYTES>>>(images, mats, out);
}

// round 10
// speedup vs baseline: 5.2194x; 1.0881x over previous
#include <cuda_runtime.h>
#include <cuda_fp16.h>
#include <cuda_bf16.h>

#define SRC_H 512
#define SRC_W 512
#define NCH   3
#define OUT_N 224
#define TOX   32
#define TOY   14
#define NTAP  6
#define NIX   79
#define NIY   37
#define WPITCH 82                 // skewed s_w pitch
#define NTHREADS 256

#define SH_T   56                 // staged rows capacity
#define SW_PX  100                // staged pixels per row
#define ROWF  (SRC_W * NCH)
#define IMG3F ((size_t)SRC_H * SRC_W * NCH)
#define TOTF  ((size_t)32 * IMG3F)

// dynamic smem layout (bytes)
#define OFF_SRG 0
#define SZ_SRG  (SH_T * SW_PX * 4)        // 22400  RG plane (half2/px)
#define OFF_SB  (OFF_SRG + SZ_SRG)
#define SZ_SB   (SH_T * SW_PX * 2)        // 11200  B plane (half/px)
#define OFF_WRG (OFF_SB + SZ_SB)          // 33600
#define SZ_WRG  (NIY * WPITCH * 4)        // 12136
#define OFF_WB  (OFF_WRG + SZ_WRG)
#define SZ_WB   (NIY * WPITCH * 2)        // 6068
#define DYN_BYTES (OFF_WB + SZ_WB + 4)    // 51808
// s_t aliases the staging region (dead after stage 1): 14208 <= 33600
#define OFF_TRG 0
#define OFF_TB  (NIY * TOX * 8)           // 9472

__device__ __forceinline__ unsigned h2u(__half2 h) {
    return *reinterpret_cast<unsigned*>(&h);
}

__global__ __launch_bounds__(NTHREADS, 4) void warp_resize_kernel(
    const float* __restrict__ images,   // (32, 512, 512, 3)
    const float* __restrict__ mats,     // (32, 2, 3)
    float* __restrict__ out)            // (32, 224, 224, 3)
{
    extern __shared__ __align__(16) unsigned char dynraw[];
    __half2* s_RG  = (__half2*)(dynraw + OFF_SRG);     // staged RG plane, pitch SW_PX
    __half*  s_B   = (__half*) (dynraw + OFF_SB);      // staged B plane, pitch SW_PX
    __half2* s_wRG = (__half2*)(dynraw + OFF_WRG);     // warped RG, skewed pitch
    __half*  s_wB  = (__half*) (dynraw + OFF_WB);      // warped B, skewed pitch
    float2*  s_tRG = (float2*) (dynraw + OFF_TRG);     // aliases staging (stage2+)
    float*   s_tB  = (float*)  (dynraw + OFF_TB);

    __shared__ float s_wx[TOX][NTAP];
    __shared__ float s_wy[TOY][NTAP];
    __shared__ int   s_bx[TOX];
    __shared__ int   s_by[TOY];

    const int b    = blockIdx.z;
    const int ox0  = blockIdx.x * TOX;
    const int oy0  = blockIdx.y * TOY;
    const int tid  = threadIdx.x;
    const int wrp  = tid >> 5;
    const int lane = tid & 31;

    const float INV = 512.0f / 224.0f;
    const float SC  = 224.0f / 512.0f;

    const int IX0 = (int)floorf((ox0 + 0.5f) * INV - 0.5f) - 2;
    const int IY0 = (int)floorf((oy0 + 0.5f) * INV - 0.5f) - 2;

    // ---- Resize weights (normalized triangle kernel, jax semantics) ----
    if (tid < TOX) {
        int j = ox0 + tid;
        float sf = (j + 0.5f) * INV - 0.5f;
        int i0 = (int)floorf(sf) - 2;
        float wv[NTAP];
        float sum = 0.0f;
        #pragma unroll
        for (int k = 0; k < NTAP; k++) {
            int i = i0 + k;
            float w = fmaxf(1.0f - fabsf(sf - (float)i) * SC, 0.0f);
            if (i < 0 || i >= SRC_W) w = 0.0f;
            wv[k] = w; sum += w;
        }
        float inv = 1.0f / sum;
        #pragma unroll
        for (int k = 0; k < NTAP; k++) s_wx[tid][k] = wv[k] * inv;
        s_bx[tid] = i0 - IX0;
    } else if (tid < TOX + TOY) {
        int t = tid - TOX;
        int j = oy0 + t;
        float sf = (j + 0.5f) * INV - 0.5f;
        int i0 = (int)floorf(sf) - 2;
        float wv[NTAP];
        float sum = 0.0f;
        #pragma unroll
        for (int k = 0; k < NTAP; k++) {
            int i = i0 + k;
            float w = fmaxf(1.0f - fabsf(sf - (float)i) * SC, 0.0f);
            if (i < 0 || i >= SRC_H) w = 0.0f;
            wv[k] = w; sum += w;
        }
        float inv = 1.0f / sum;
        #pragma unroll
        for (int k = 0; k < NTAP; k++) s_wy[t][k] = wv[k] * inv;
        s_by[t] = i0 - IY0;
    }

    const float* Mp = mats + b * 6;
    const float M00 = __ldg(Mp + 0), M01 = __ldg(Mp + 1), M02 = __ldg(Mp + 2);
    const float M10 = __ldg(Mp + 3), M11 = __ldg(Mp + 4), M12 = __ldg(Mp + 5);

    const float* img = images + (size_t)b * IMG3F;

    // ---- Exact affine bbox of the warped tile's source footprint ----
    const float gy0 = (float)IY0, gy1 = (float)(IY0 + NIY - 1);
    const float gx0 = (float)IX0, gx1 = (float)(IX0 + NIX - 1);

    float sy00 = fmaf(M00, gy0, fmaf(M01, gx0, M02));
    float sy01 = fmaf(M00, gy0, fmaf(M01, gx1, M02));
    float sy10 = fmaf(M00, gy1, fmaf(M01, gx0, M02));
    float sy11 = fmaf(M00, gy1, fmaf(M01, gx1, M02));
    float sx00 = fmaf(M10, gy0, fmaf(M11, gx0, M12));
    float sx01 = fmaf(M10, gy0, fmaf(M11, gx1, M12));
    float sx10 = fmaf(M10, gy1, fmaf(M11, gx0, M12));
    float sx11 = fmaf(M10, gy1, fmaf(M11, gx1, M12));

    float symin = fminf(fminf(sy00, sy01), fminf(sy10, sy11));
    float symax = fmaxf(fmaxf(sy00, sy01), fmaxf(sy10, sy11));
    float sxmin = fminf(fminf(sx00, sx01), fminf(sx10, sx11));
    float sxmax = fmaxf(fmaxf(sx00, sx01), fmaxf(sx10, sx11));

    int fy0 = (int)floorf(symin) - 1;
    int fy1 = (int)floorf(symax) + 2;
    int fx0 = (int)floorf(sxmin) - 1;
    int fx1 = (int)floorf(sxmax) + 2;

    bool interior = (fy0 >= 0) && (fy1 < SRC_H) && (fx0 >= 0) && (fx1 < SRC_W);

    int by0 = max(0, fy0);
    int by1 = min(SRC_H - 1, fy1);
    int bx0 = max(0, fx0) & ~3;            // 4-px align for float4 staging
    int bx1 = min(SRC_W - 1, fx1);

    int hgt = by1 - by0 + 1;
    int wid = bx1 - bx0 + 1;
    bool staged = (hgt > 0) && (wid > 0) && (hgt <= SH_T) && (wid <= SW_PX);

    // ---- Stage source box: fp32 interleaved -> SMEM planar fp16 (RG half2 + B half) ----
    if (staged) {
        size_t base_f = (size_t)b * IMG3F + ((size_t)by0 * SRC_W + bx0) * NCH;
        for (int r = wrp; r < hgt; r += 8) {
            if (lane < 25) {                       // 25 lanes x 4 px = 100 px/row
                size_t fidx = base_f + (size_t)r * ROWF + (size_t)lane * 12;
                float f[12];
                if (fidx + 12 <= TOTF) {
                    const float4* g = (const float4*)(images + fidx);
                    float4 a = g[0], bq = g[1], cq = g[2];
                    f[0]=a.x; f[1]=a.y; f[2]=a.z; f[3]=a.w;
                    f[4]=bq.x; f[5]=bq.y; f[6]=bq.z; f[7]=bq.w;
                    f[8]=cq.x; f[9]=cq.y; f[10]=cq.z; f[11]=cq.w;
                } else {
                    #pragma unroll
                    for (int k = 0; k < 12; k++)
                        f[k] = (fidx + k < TOTF) ? images[fidx + k] : 0.0f;
                }
                uint4 rg;
                rg.x = h2u(__floats2half2_rn(f[0], f[1]));
                rg.y = h2u(__floats2half2_rn(f[3], f[4]));
                rg.z = h2u(__floats2half2_rn(f[6], f[7]));
                rg.w = h2u(__floats2half2_rn(f[9], f[10]));
                uint2 bb;
                bb.x = h2u(__floats2half2_rn(f[2], f[5]));
                bb.y = h2u(__floats2half2_rn(f[8], f[11]));
                *(uint4*)(s_RG + r * SW_PX + lane * 4) = rg;
                *(uint2*)(s_B  + r * SW_PX + lane * 4) = bb;
            }
        }
    }
    __syncthreads();

    // ---- Stage 1: warped tile ----
    const float by0f = (float)by0;
    const float bx0f = (float)bx0;

    for (int ty = wrp; ty < NIY; ty += 8) {
        float gy = (float)(IY0 + ty);
        float sybA = fmaf(M00, gy, M02);               // absolute bases
        float sxbA = fmaf(M10, gy, M12);

        if (staged && interior) {
            float sybR = sybA - by0f;
            float sxbR = sxbA - bx0f;
            #pragma unroll
            for (int c = 0; c < 3; c++) {
                int tx = c * 32 + lane;
                if (tx < NIX) {
                    float gx = (float)(IX0 + tx);
                    float syr = fmaf(M01, gx, sybR);
                    float sxr = fmaf(M11, gx, sxbR);
                    float fy = floorf(syr), fxx = floorf(sxr);
                    float ay = syr - fy,   ax = sxr - fxx;
                    int iy = (int)fy, ix = (int)fxx;

                    float oy_ = 1.0f - ay, oxx = 1.0f - ax;
                    float w00 = oy_ * oxx, w01 = oy_ * ax;
                    float w10 = ay * oxx,  w11 = ay * ax;

                    const __half2* r0 = s_RG + iy * SW_PX + ix;
                    __half2 q00 = r0[0], q01 = r0[1];
                    __half2 q10 = r0[SW_PX], q11 = r0[SW_PX + 1];
                    const __half* rb = s_B + iy * SW_PX + ix;
                    float b00 = __half2float(rb[0]);
                    float b01 = __half2float(rb[1]);
                    float b10 = __half2float(rb[SW_PX]);
                    float b11 = __half2float(rb[SW_PX + 1]);

                    __half2 aRG = __hmul2(__float2half2_rn(w00), q00);
                    aRG = __hfma2(__float2half2_rn(w01), q01, aRG);
                    aRG = __hfma2(__float2half2_rn(w10), q10, aRG);
                    aRG = __hfma2(__float2half2_rn(w11), q11, aRG);
                    float bl = w00 * b00 + w01 * b01 + w10 * b10 + w11 * b11;

                    int idx = tx + (tx >> 5);
                    s_wRG[ty * WPITCH + idx] = aRG;
                    s_wB [ty * WPITCH + idx] = __float2half_rn(bl);
                }
            }
        } else if (staged) {
            // border tile: validity-zeroed weights + clamped in-box indices
            #pragma unroll
            for (int c = 0; c < 3; c++) {
                int tx = c * 32 + lane;
                if (tx < NIX) {
                    float gx = (float)(IX0 + tx);
                    float sy = fmaf(M01, gx, sybA);
                    float sx = fmaf(M11, gx, sxbA);
                    float fy = floorf(sy), fxx = floorf(sx);
                    float ay = sy - fy,   ax = sx - fxx;
                    int iy = (int)fy, ix = (int)fxx;
                    int iy1 = iy + 1, ix1 = ix + 1;

                    float wy0 = ((unsigned)iy  < (unsigned)SRC_H) ? (1.0f - ay) : 0.0f;
                    float wy1 = ((unsigned)iy1 < (unsigned)SRC_H) ? ay : 0.0f;
                    float wx0v = ((unsigned)ix  < (unsigned)SRC_W) ? (1.0f - ax) : 0.0f;
                    float wx1v = ((unsigned)ix1 < (unsigned)SRC_W) ? ax : 0.0f;
                    float w00 = wy0 * wx0v, w01 = wy0 * wx1v;
                    float w10 = wy1 * wx0v, w11 = wy1 * wx1v;

                    int ry0 = min(max(iy  - by0, 0), hgt - 1);
                    int ry1 = min(max(iy1 - by0, 0), hgt - 1);
                    int rx0 = min(max(ix  - bx0, 0), wid - 1);
                    int rx1 = min(max(ix1 - bx0, 0), wid - 1);

                    __half2 q00 = s_RG[ry0 * SW_PX + rx0];
                    __half2 q01 = s_RG[ry0 * SW_PX + rx1];
                    __half2 q10 = s_RG[ry1 * SW_PX + rx0];
                    __half2 q11 = s_RG[ry1 * SW_PX + rx1];
                    float b00 = __half2float(s_B[ry0 * SW_PX + rx0]);
                    float b01 = __half2float(s_B[ry0 * SW_PX + rx1]);
                    float b10 = __half2float(s_B[ry1 * SW_PX + rx0]);
                    float b11 = __half2float(s_B[ry1 * SW_PX + rx1]);

                    __half2 aRG = __hmul2(__float2half2_rn(w00), q00);
                    aRG = __hfma2(__float2half2_rn(w01), q01, aRG);
                    aRG = __hfma2(__float2half2_rn(w10), q10, aRG);
                    aRG = __hfma2(__float2half2_rn(w11), q11, aRG);
                    float bl = w00 * b00 + w01 * b01 + w10 * b10 + w11 * b11;

                    int idx = tx + (tx >> 5);
                    s_wRG[ty * WPITCH + idx] = aRG;
                    s_wB [ty * WPITCH + idx] = __float2half_rn(bl);
                }
            }
        } else {
            // fallback: global fp32 gather (correctness safety net)
            #pragma unroll 1
            for (int c = 0; c < 3; c++) {
                int tx = c * 32 + lane;
                if (tx < NIX) {
                    float gx = (float)(IX0 + tx);
                    float sy = fmaf(M01, gx, sybA);
                    float sx = fmaf(M11, gx, sxbA);
                    float fy = floorf(sy), fxx = floorf(sx);
                    float ay = sy - fy,   ax = sx - fxx;
                    int iy = (int)fy, ix = (int)fxx;
                    int iy1 = iy + 1, ix1 = ix + 1;

                    float wy0 = ((unsigned)iy  < (unsigned)SRC_H) ? (1.0f - ay) : 0.0f;
                    float wy1 = ((unsigned)iy1 < (unsigned)SRC_H) ? ay : 0.0f;
                    float wx0v = ((unsigned)ix  < (unsigned)SRC_W) ? (1.0f - ax) : 0.0f;
                    float wx1v = ((unsigned)ix1 < (unsigned)SRC_W) ? ax : 0.0f;
                    float w00 = wy0 * wx0v, w01 = wy0 * wx1v;
                    float w10 = wy1 * wx0v, w11 = wy1 * wx1v;

                    int cy0 = min(max(iy, 0), SRC_H - 1);
                    int cy1 = min(max(iy1, 0), SRC_H - 1);
                    int cx0 = min(max(ix, 0), SRC_W - 1);
                    int cx1 = min(max(ix1, 0), SRC_W - 1);
                    const float* p00 = img + ((size_t)cy0 * SRC_W + cx0) * NCH;
                    const float* p01 = img + ((size_t)cy0 * SRC_W + cx1) * NCH;
                    const float* p10 = img + ((size_t)cy1 * SRC_W + cx0) * NCH;
                    const float* p11 = img + ((size_t)cy1 * SRC_W + cx1) * NCH;
                    float r  = w00 * p00[0] + w01 * p01[0] + w10 * p10[0] + w11 * p11[0];
                    float g  = w00 * p00[1] + w01 * p01[1] + w10 * p10[1] + w11 * p11[1];
                    float bl = w00 * p00[2] + w01 * p01[2] + w10 * p10[2] + w11 * p11[2];

                    int idx = tx + (tx >> 5);
                    s_wRG[ty * WPITCH + idx] = __floats2half2_rn(r, g);
                    s_wB [ty * WPITCH + idx] = __float2half_rn(bl);
                }
            }
        }
    }
    __syncthreads();

    // ---- Stage 2: x-convolution (6 taps, fp32 accum, skewed reads) ----
    {
        int ox  = tid & 31;                 // invariant across iterations
        int base = s_bx[ox];
        float w0 = s_wx[ox][0], w1 = s_wx[ox][1], w2 = s_wx[ox][2];
        float w3 = s_wx[ox][3], w4 = s_wx[ox][4], w5 = s_wx[ox][5];
        for (int ty = tid >> 5; ty < NIY; ty += 8) {
            const __half2* rowRG = s_wRG + ty * WPITCH;
            const __half*  rowB  = s_wB  + ty * WPITCH;
            float a0 = 0.0f, a1 = 0.0f, a2 = 0.0f;
            #pragma unroll
            for (int k = 0; k < NTAP; k++) {
                float w = (k == 0) ? w0 : (k == 1) ? w1 : (k == 2) ? w2
                        : (k == 3) ? w3 : (k == 4) ? w4 : w5;
                int wdx = base + k;
                int idx = wdx + (wdx >> 5);
                float2 f = __half22float2(rowRG[idx]);
                a0 = fmaf(w, f.x, a0);
                a1 = fmaf(w, f.y, a1);
                a2 = fmaf(w, __half2float(rowB[idx]), a2);
            }
            s_tRG[ty * TOX + ox] = make_float2(a0, a1);
            s_tB [ty * TOX + ox] = a2;
        }
    }
    __syncthreads();

    // ---- Stage 3: y-convolution (6 taps) + store ----
    {
        int ox = tid & 31;
        for (int oy = tid >> 5; oy < TOY; oy += 8) {
            int base = s_by[oy];
            float a0 = 0.0f, a1 = 0.0f, a2 = 0.0f;
            #pragma unroll
            for (int k = 0; k < NTAP; k++) {
                float w = s_wy[oy][k];
                float2 f = s_tRG[(base + k) * TOX + ox];
                a0 = fmaf(w, f.x, a0);
                a1 = fmaf(w, f.y, a1);
                a2 = fmaf(w, s_tB[(base + k) * TOX + ox], a2);
            }
            float* op = out + (((size_t)b * OUT_N + (oy0 + oy)) * OUT_N + (ox0 + ox)) * NCH;
            op[0] = a0;
            op[1] = a1;
            op[2] = a2;
        }
    }
}

extern "C" void kernel_launch(void* const* d_in, const int* in_sizes, int n_in,
                              void* d_out, int out_size)
{
    const float* images = (const float*)d_in[0];
    const float* mats   = (const float*)d_in[1];
    float* out = (float*)d_out;

    cudaFuncSetAttribute(warp_resize_kernel,
                         cudaFuncAttributeMaxDynamicSharedMemorySize, DYN_BYTES);

    dim3 grid(OUT_N / TOX, OUT_N / TOY, 32);   // 7 x 16 x 32
    warp_resize_kernel<<<grid, NTHREADS, DYN_BYTES>>>(images, mats, out);
}